// round 2
// baseline (speedup 1.0000x reference)
#include <cuda_runtime.h>

#define NN 100000
#define EE 1600000
#define ET 1700000            // EE + NN self loops
#define NSCAN_BLK 98          // ceil(NN/1024)
#define FULLMASK 0xffffffffu

// ---------------- scratch (static device globals: no runtime allocation) ----
__device__ float g_xl1[NN * 128];
__device__ float g_xr1[NN * 128];
__device__ float g_h1 [NN * 128];
__device__ float g_xl2[NN * 32];
__device__ float g_xr2[NN * 32];
__device__ float g_sc1[ET * 4];        // layer-1 scores in CSR order
__device__ int   g_deg[NN];
__device__ int   g_cnt[NN];
__device__ int   g_rowptr[NN + 1];
__device__ int   g_esrc[ET];
__device__ int   g_eid [ET];
__device__ int   g_bsum[NSCAN_BLK];
__device__ float g_bnsum[128], g_bnsq[128];
__device__ float g_bnscale[128], g_bnshift[128];
__device__ int   g_is64;

// ---------------- helpers ---------------------------------------------------
__device__ __forceinline__ float wred(float v) {
    v += __shfl_xor_sync(FULLMASK, v, 16);
    v += __shfl_xor_sync(FULLMASK, v, 8);
    v += __shfl_xor_sync(FULLMASK, v, 4);
    v += __shfl_xor_sync(FULLMASK, v, 2);
    v += __shfl_xor_sync(FULLMASK, v, 1);
    return v;
}
__device__ __forceinline__ float lrelu(float v, float s) { return v > 0.f ? v : s * v; }

__device__ __forceinline__ int get_edge(const void* ei, int which, int e) {
    if (g_is64) return (int)((const long long*)ei)[(size_t)which * EE + e];
    return ((const int*)ei)[(size_t)which * EE + e];
}

// edge_index dtype probe: int64 little-endian nonneg values < 2^31 -> every
// odd 32-bit word is zero. 64 random int32 node ids in [0,1e5) would be
// nonzero in those slots with overwhelming probability.
__global__ void detect_k(const int* ei) {
    if (blockIdx.x == 0 && threadIdx.x == 0) {
        int z = 1;
        for (int i = 1; i < 129; i += 2) if (ei[i] != 0) { z = 0; break; }
        g_is64 = z;
    }
}

__global__ void init_k() {
    int i = blockIdx.x * blockDim.x + threadIdx.x;
    if (i < NN) { g_deg[i] = 0; g_cnt[i] = 0; }
    if (i < 128) { g_bnsum[i] = 0.f; g_bnsq[i] = 0.f; }
}

// ---------------- GEMM 1: xl1 = x@Wl1, xr1 = x@Wr1  (K=128, Fout=128) -------
__global__ void gemm1_k(const float* __restrict__ x,
                        const float* __restrict__ Wl,
                        const float* __restrict__ Wr) {
    __shared__ float As[64][68];
    __shared__ float Bs[64][64];
    int cb = blockIdx.y;                       // 0,1 -> Wl ; 2,3 -> Wr
    const float* W = (cb < 2) ? Wl : Wr;
    float* out = (cb < 2) ? g_xl1 : g_xr1;
    int colbase = (cb & 1) * 64;
    int rowbase = blockIdx.x * 64;
    int tid = threadIdx.x, tx = tid & 15, ty = tid >> 4;
    float acc[4][4];
#pragma unroll
    for (int i = 0; i < 4; i++)
#pragma unroll
        for (int j = 0; j < 4; j++) acc[i][j] = 0.f;

    for (int kb = 0; kb < 128; kb += 64) {
#pragma unroll
        for (int p = 0; p < 4; p++) {
            int lin = (p * 256 + tid) * 4;
            int r = lin >> 6, kk = lin & 63;
            int grow = rowbase + r;
            float4 v = make_float4(0.f, 0.f, 0.f, 0.f);
            if (grow < NN) v = *(const float4*)&x[(size_t)grow * 128 + kb + kk];
            *(float4*)&As[r][kk] = v;
        }
#pragma unroll
        for (int p = 0; p < 4; p++) {
            int lin = (p * 256 + tid) * 4;
            int kk = lin >> 6, c = lin & 63;
            float4 v = *(const float4*)&W[(size_t)(kb + kk) * 128 + colbase + c];
            *(float4*)&Bs[kk][c] = v;
        }
        __syncthreads();
#pragma unroll
        for (int kk = 0; kk < 64; kk++) {
            float4 bv = *(float4*)&Bs[kk][tx * 4];
            float av[4];
#pragma unroll
            for (int i = 0; i < 4; i++) av[i] = As[ty * 4 + i][kk];
#pragma unroll
            for (int i = 0; i < 4; i++) {
                acc[i][0] += av[i] * bv.x;
                acc[i][1] += av[i] * bv.y;
                acc[i][2] += av[i] * bv.z;
                acc[i][3] += av[i] * bv.w;
            }
        }
        __syncthreads();
    }
#pragma unroll
    for (int i = 0; i < 4; i++) {
        int grow = rowbase + ty * 4 + i;
        if (grow < NN) {
#pragma unroll
            for (int j = 0; j < 4; j++)
                out[(size_t)grow * 128 + colbase + tx * 4 + j] = acc[i][j];
        }
    }
}

// ---------------- CSR build -------------------------------------------------
__global__ void hist_k(const void* ei) {
    int e = blockIdx.x * blockDim.x + threadIdx.x;
    if (e >= ET) return;
    int d = (e < EE) ? get_edge(ei, 1, e) : (e - EE);
    atomicAdd(&g_deg[d], 1);
}

__global__ void scan1_k() {
    __shared__ int sm[1024];
    int t = threadIdx.x;
    int i = blockIdx.x * 1024 + t;
    int v = (i < NN) ? g_deg[i] : 0;
    sm[t] = v;
    __syncthreads();
    for (int off = 1; off < 1024; off <<= 1) {
        int u = (t >= off) ? sm[t - off] : 0;
        __syncthreads();
        sm[t] += u;
        __syncthreads();
    }
    if (i < NN) g_rowptr[i + 1] = sm[t];
    if (t == 1023) g_bsum[blockIdx.x] = sm[1023];
}

__global__ void scan2_k() {
    if (threadIdx.x == 0 && blockIdx.x == 0) {
        int run = 0;
        for (int i = 0; i < NSCAN_BLK; i++) { run += g_bsum[i]; g_bsum[i] = run; }
    }
}

__global__ void scan3_k() {
    int i = blockIdx.x * blockDim.x + threadIdx.x;
    if (i == 0) g_rowptr[0] = 0;
    if (i < NN) {
        int b = i >> 10;
        if (b > 0) g_rowptr[i + 1] += g_bsum[b - 1];
    }
}

__global__ void scatter_k(const void* ei) {
    int e = blockIdx.x * blockDim.x + threadIdx.x;
    if (e >= ET) return;
    int s, d;
    if (e < EE) { s = get_edge(ei, 0, e); d = get_edge(ei, 1, e); }
    else        { s = e - EE; d = e - EE; }
    int pos = g_rowptr[d] + atomicAdd(&g_cnt[d], 1);
    g_esrc[pos] = s;
    g_eid[pos]  = e;
}

// ---------------- conv1: warp per dst node, online softmax -----------------
__global__ void conv1_k(const float* __restrict__ att1, const float* __restrict__ b1,
                        float* __restrict__ out_alpha) {
    int w = (blockIdx.x * blockDim.x + threadIdx.x) >> 5;
    if (w >= NN) return;
    int l = threadIdx.x & 31;
    const float* xrp = &g_xr1[(size_t)w * 128];
    float r0 = xrp[l], r1 = xrp[32 + l], r2 = xrp[64 + l], r3 = xrp[96 + l];
    float t0 = att1[l], t1 = att1[32 + l], t2 = att1[64 + l], t3 = att1[96 + l];
    float m0 = -1e30f, m1 = -1e30f, m2 = -1e30f, m3 = -1e30f;
    float s0 = 0.f, s1 = 0.f, s2 = 0.f, s3 = 0.f;
    float a0 = 0.f, a1 = 0.f, a2 = 0.f, a3 = 0.f;
    int beg = g_rowptr[w], end = g_rowptr[w + 1];
    for (int i = beg; i < end; i++) {
        int sn = g_esrc[i];
        const float* xp = &g_xl1[(size_t)sn * 128];
        float x0 = xp[l], x1 = xp[32 + l], x2 = xp[64 + l], x3 = xp[96 + l];
        float p0 = t0 * lrelu(x0 + r0, 0.2f);
        float p1 = t1 * lrelu(x1 + r1, 0.2f);
        float p2 = t2 * lrelu(x2 + r2, 0.2f);
        float p3 = t3 * lrelu(x3 + r3, 0.2f);
        p0 = wred(p0); p1 = wred(p1); p2 = wred(p2); p3 = wred(p3);
        if (l == 0) *(float4*)&g_sc1[(size_t)i * 4] = make_float4(p0, p1, p2, p3);
        float nm, cc, wt;
        nm = fmaxf(m0, p0); cc = __expf(m0 - nm); wt = __expf(p0 - nm);
        s0 = s0 * cc + wt; a0 = a0 * cc + wt * x0; m0 = nm;
        nm = fmaxf(m1, p1); cc = __expf(m1 - nm); wt = __expf(p1 - nm);
        s1 = s1 * cc + wt; a1 = a1 * cc + wt * x1; m1 = nm;
        nm = fmaxf(m2, p2); cc = __expf(m2 - nm); wt = __expf(p2 - nm);
        s2 = s2 * cc + wt; a2 = a2 * cc + wt * x2; m2 = nm;
        nm = fmaxf(m3, p3); cc = __expf(m3 - nm); wt = __expf(p3 - nm);
        s3 = s3 * cc + wt; a3 = a3 * cc + wt * x3; m3 = nm;
    }
    float* hp = &g_h1[(size_t)w * 128];
    hp[l]      = a0 / (s0 + 1e-16f) + b1[l];
    hp[32 + l] = a1 / (s1 + 1e-16f) + b1[32 + l];
    hp[64 + l] = a2 / (s2 + 1e-16f) + b1[64 + l];
    hp[96 + l] = a3 / (s3 + 1e-16f) + b1[96 + l];
    // alpha pass: 8 edges x 4 heads per iteration
    int hh = l & 3, eo = l >> 2;
    float mh = (hh == 0) ? m0 : (hh == 1) ? m1 : (hh == 2) ? m2 : m3;
    float sh = ((hh == 0) ? s0 : (hh == 1) ? s1 : (hh == 2) ? s2 : s3) + 1e-16f;
    float inv_sh = 1.f / sh;
    for (int i = beg + eo; i < end; i += 8) {
        float sc = g_sc1[(size_t)i * 4 + hh];
        int oe = g_eid[i];
        out_alpha[(size_t)oe * 4 + hh] = __expf(sc - mh) * inv_sh;
    }
}

// ---------------- BatchNorm stats ------------------------------------------
__global__ void bnstats_k() {
    int c = threadIdx.x;
    float s = 0.f, sq = 0.f;
    for (int r = blockIdx.x; r < NN; r += gridDim.x) {
        float v = g_h1[(size_t)r * 128 + c];
        s += v; sq += v * v;
    }
    atomicAdd(&g_bnsum[c], s);
    atomicAdd(&g_bnsq[c], sq);
}

__global__ void bnfin_k(const float* __restrict__ gamma, const float* __restrict__ beta) {
    int c = threadIdx.x;
    float mu = g_bnsum[c] * (1.f / NN);
    float var = g_bnsq[c] * (1.f / NN) - mu * mu;
    float sc = gamma[c] * rsqrtf(var + 1e-5f);
    g_bnscale[c] = sc;
    g_bnshift[c] = beta[c] - mu * sc;
}

// ---------------- GEMM 2: (BN+lrelu fused) xl2/xr2 = h1n @ [Wl2|Wr2] -------
__global__ void gemm2_k(const float* __restrict__ Wl2, const float* __restrict__ Wr2) {
    __shared__ float As[64][68];
    __shared__ float Bs[64][64];
    int rowbase = blockIdx.x * 64;
    int tid = threadIdx.x, tx = tid & 15, ty = tid >> 4;
    float acc[4][4];
#pragma unroll
    for (int i = 0; i < 4; i++)
#pragma unroll
        for (int j = 0; j < 4; j++) acc[i][j] = 0.f;

    for (int kb = 0; kb < 128; kb += 64) {
#pragma unroll
        for (int p = 0; p < 4; p++) {
            int lin = (p * 256 + tid) * 4;
            int r = lin >> 6, kk = lin & 63;
            int grow = rowbase + r;
            float4 v = make_float4(0.f, 0.f, 0.f, 0.f);
            if (grow < NN) {
                v = *(const float4*)&g_h1[(size_t)grow * 128 + kb + kk];
                int c = kb + kk;
                v.x = lrelu(v.x * g_bnscale[c]     + g_bnshift[c],     0.01f);
                v.y = lrelu(v.y * g_bnscale[c + 1] + g_bnshift[c + 1], 0.01f);
                v.z = lrelu(v.z * g_bnscale[c + 2] + g_bnshift[c + 2], 0.01f);
                v.w = lrelu(v.w * g_bnscale[c + 3] + g_bnshift[c + 3], 0.01f);
            }
            *(float4*)&As[r][kk] = v;
        }
#pragma unroll
        for (int p = 0; p < 4; p++) {
            int lin = (p * 256 + tid) * 4;
            int kk = lin >> 6, c = lin & 63;
            float4 v;
            if (c < 32) v = *(const float4*)&Wl2[(size_t)(kb + kk) * 32 + c];
            else        v = *(const float4*)&Wr2[(size_t)(kb + kk) * 32 + (c - 32)];
            *(float4*)&Bs[kk][c] = v;
        }
        __syncthreads();
#pragma unroll
        for (int kk = 0; kk < 64; kk++) {
            float4 bv = *(float4*)&Bs[kk][tx * 4];
            float av[4];
#pragma unroll
            for (int i = 0; i < 4; i++) av[i] = As[ty * 4 + i][kk];
#pragma unroll
            for (int i = 0; i < 4; i++) {
                acc[i][0] += av[i] * bv.x;
                acc[i][1] += av[i] * bv.y;
                acc[i][2] += av[i] * bv.z;
                acc[i][3] += av[i] * bv.w;
            }
        }
        __syncthreads();
    }
#pragma unroll
    for (int i = 0; i < 4; i++) {
        int grow = rowbase + ty * 4 + i;
        if (grow < NN) {
#pragma unroll
            for (int j = 0; j < 4; j++) {
                int col = tx * 4 + j;
                if (col < 32) g_xl2[(size_t)grow * 32 + col]        = acc[i][j];
                else          g_xr2[(size_t)grow * 32 + (col - 32)] = acc[i][j];
            }
        }
    }
}

// ---------------- conv2 + leaky + Wout + log_softmax ------------------------
__global__ void conv2_k(const float* __restrict__ att2, const float* __restrict__ b2,
                        const float* __restrict__ Wout, const float* __restrict__ bout,
                        float* __restrict__ out_logp) {
    int w = (blockIdx.x * blockDim.x + threadIdx.x) >> 5;
    if (w >= NN) return;
    int l = threadIdx.x & 31;
    float xr = g_xr2[(size_t)w * 32 + l];
    float at = att2[l];
    float m = -1e30f, s = 0.f, a = 0.f;
    int beg = g_rowptr[w], end = g_rowptr[w + 1];
    for (int i = beg; i < end; i++) {
        int sn = g_esrc[i];
        float xv = g_xl2[(size_t)sn * 32 + l];
        float p = at * lrelu(xv + xr, 0.2f);
        p = wred(p);
        float nm = fmaxf(m, p);
        float cc = __expf(m - nm);
        float wt = __expf(p - nm);
        s = s * cc + wt;
        a = a * cc + wt * xv;
        m = nm;
    }
    float h = a / (s + 1e-16f) + b2[l];
    h = lrelu(h, 0.01f);
    float q0 = h * Wout[l * 3 + 0];
    float q1 = h * Wout[l * 3 + 1];
    float q2 = h * Wout[l * 3 + 2];
    q0 = wred(q0) + bout[0];
    q1 = wred(q1) + bout[1];
    q2 = wred(q2) + bout[2];
    float mx = fmaxf(q0, fmaxf(q1, q2));
    float lse = logf(expf(q0 - mx) + expf(q1 - mx) + expf(q2 - mx)) + mx;
    if (l < 3) {
        float z = (l == 0) ? q0 : (l == 1) ? q1 : q2;
        out_logp[(size_t)w * 3 + l] = z - lse;
    }
}

// ---------------- launcher --------------------------------------------------
extern "C" void kernel_launch(void* const* d_in, const int* in_sizes, int n_in,
                              void* d_out, int out_size) {
    const float* x     = (const float*)d_in[0];
    const void*  ei    = d_in[1];
    const float* Wl1   = (const float*)d_in[2];
    const float* Wr1   = (const float*)d_in[3];
    const float* att1  = (const float*)d_in[4];
    const float* b1    = (const float*)d_in[5];
    const float* gamma = (const float*)d_in[6];
    const float* beta  = (const float*)d_in[7];
    const float* Wl2   = (const float*)d_in[8];
    const float* Wr2   = (const float*)d_in[9];
    const float* att2  = (const float*)d_in[10];
    const float* b2    = (const float*)d_in[11];
    const float* Wout  = (const float*)d_in[12];
    const float* bout  = (const float*)d_in[13];
    float* out       = (float*)d_out;
    float* out_logp  = out;
    float* out_alpha = out + (size_t)NN * 3;

    detect_k<<<1, 32>>>((const int*)ei);
    init_k<<<(NN + 255) / 256, 256>>>();
    gemm1_k<<<dim3((NN + 63) / 64, 4), 256>>>(x, Wl1, Wr1);
    hist_k<<<(ET + 255) / 256, 256>>>(ei);
    scan1_k<<<NSCAN_BLK, 1024>>>();
    scan2_k<<<1, 32>>>();
    scan3_k<<<(NN + 255) / 256, 256>>>();
    scatter_k<<<(ET + 255) / 256, 256>>>(ei);
    conv1_k<<<(NN * 32 + 255) / 256, 256>>>(att1, b1, out_alpha);
    bnstats_k<<<512, 128>>>();
    bnfin_k<<<1, 128>>>(gamma, beta);
    gemm2_k<<<(NN + 63) / 64, 256>>>(Wl2, Wr2);
    conv2_k<<<(NN * 32 + 255) / 256, 256>>>(att2, b2, Wout, bout, out_logp);
}

// round 3
// speedup vs baseline: 1.3157x; 1.3157x over previous
#include <cuda_runtime.h>

#define NN 100000
#define EE 1600000
#define ET 1700000            // EE + NN self loops
#define NSCAN_BLK 98          // ceil(NN/1024)
#define FULLMASK 0xffffffffu

typedef unsigned long long ull;

// ---------------- scratch (static device globals: no runtime allocation) ----
__device__ float g_xl1[NN * 128];
__device__ float g_xr1[NN * 128];
__device__ float g_h1 [NN * 128];
__device__ float g_xl2[NN * 32];
__device__ float g_xr2[NN * 32];
__device__ float g_sc1[ET * 4];        // layer-1 scores in CSR order
__device__ int   g_deg[NN];
__device__ int   g_cnt[NN];
__device__ int   g_rowptr[NN + 1];
__device__ int   g_esrc[ET];
__device__ int   g_eid [ET];
__device__ int   g_bsum[NSCAN_BLK];
__device__ float g_bnsum[128], g_bnsq[128];
__device__ float g_bnscale[128], g_bnshift[128];
__device__ int   g_is64;

// ---------------- helpers ---------------------------------------------------
__device__ __forceinline__ ull fma2(ull a, ull b, ull c) {
    ull d; asm("fma.rn.f32x2 %0, %1, %2, %3;" : "=l"(d) : "l"(a), "l"(b), "l"(c)); return d;
}
__device__ __forceinline__ ull pack2(float lo, float hi) {
    ull r; asm("mov.b64 %0, {%1, %2};" : "=l"(r) : "f"(lo), "f"(hi)); return r;
}
__device__ __forceinline__ void unpack2(ull v, float& lo, float& hi) {
    asm("mov.b64 {%0, %1}, %2;" : "=f"(lo), "=f"(hi) : "l"(v));
}
__device__ __forceinline__ float wred(float v) {
    v += __shfl_xor_sync(FULLMASK, v, 16);
    v += __shfl_xor_sync(FULLMASK, v, 8);
    v += __shfl_xor_sync(FULLMASK, v, 4);
    v += __shfl_xor_sync(FULLMASK, v, 2);
    v += __shfl_xor_sync(FULLMASK, v, 1);
    return v;
}
__device__ __forceinline__ float lrelu(float v, float s) { return v > 0.f ? v : s * v; }

__device__ __forceinline__ int get_edge(const void* ei, int which, int e) {
    if (g_is64) return (int)((const long long*)ei)[(size_t)which * EE + e];
    return ((const int*)ei)[(size_t)which * EE + e];
}

// init + edge-index dtype probe (int64 nonneg -> every odd 32-bit word is 0)
__global__ void init_k(const int* ei) {
    int i = blockIdx.x * blockDim.x + threadIdx.x;
    if (i < NN) { g_deg[i] = 0; g_cnt[i] = 0; }
    if (i < 128) { g_bnsum[i] = 0.f; g_bnsq[i] = 0.f; }
    if (i == 0) {
        int z = 1;
        for (int k = 1; k < 129; k += 2) if (ei[k] != 0) { z = 0; break; }
        g_is64 = z;
    }
}

// ---------------- GEMM 1: xl1 = x@Wl1, xr1 = x@Wr1 (f32x2, 128x128 tiles) ---
__global__ __launch_bounds__(256, 2) void gemm1_k(const float* __restrict__ x,
                                                  const float* __restrict__ Wl,
                                                  const float* __restrict__ Wr) {
    __shared__ float Ast[32][130];   // A tile transposed [k][row]
    __shared__ float Bs[32][132];    // B tile [k][col]
    const float* W = blockIdx.y ? Wr : Wl;
    float* out = blockIdx.y ? g_xr1 : g_xl1;
    int rowbase = blockIdx.x * 128;
    int tid = threadIdx.x;
    int tx = tid & 15, ty = tid >> 4;
    ull acc[8][4];
#pragma unroll
    for (int i = 0; i < 8; i++)
#pragma unroll
        for (int m = 0; m < 4; m++) acc[i][m] = 0ull;

    for (int kb = 0; kb < 128; kb += 32) {
#pragma unroll
        for (int p = 0; p < 4; p++) {                 // A: 128 rows x 32 k
            int lin = p * 1024 + tid * 4;
            int r = lin >> 5, kkb = lin & 31;
            int grow = rowbase + r;
            float4 v = make_float4(0.f, 0.f, 0.f, 0.f);
            if (grow < NN) v = *(const float4*)&x[(size_t)grow * 128 + kb + kkb];
            Ast[kkb + 0][r] = v.x; Ast[kkb + 1][r] = v.y;
            Ast[kkb + 2][r] = v.z; Ast[kkb + 3][r] = v.w;
        }
#pragma unroll
        for (int p = 0; p < 4; p++) {                 // B: 32 k x 128 cols
            int lin = p * 1024 + tid * 4;
            int kk = lin >> 7, c = lin & 127;
            *(float4*)&Bs[kk][c] = *(const float4*)&W[(size_t)(kb + kk) * 128 + c];
        }
        __syncthreads();
#pragma unroll 8
        for (int kk = 0; kk < 32; kk++) {
            ull bv[4];
#pragma unroll
            for (int m = 0; m < 4; m++) bv[m] = *(ull*)&Bs[kk][2 * tx + 32 * m];
#pragma unroll
            for (int rp = 0; rp < 4; rp++) {
                float a0, a1;
                unpack2(*(ull*)&Ast[kk][ty * 8 + 2 * rp], a0, a1);
                ull d0 = pack2(a0, a0), d1 = pack2(a1, a1);
#pragma unroll
                for (int m = 0; m < 4; m++) {
                    acc[2 * rp][m]     = fma2(d0, bv[m], acc[2 * rp][m]);
                    acc[2 * rp + 1][m] = fma2(d1, bv[m], acc[2 * rp + 1][m]);
                }
            }
        }
        __syncthreads();
    }
#pragma unroll
    for (int i = 0; i < 8; i++) {
        int grow = rowbase + ty * 8 + i;
        if (grow < NN) {
#pragma unroll
            for (int m = 0; m < 4; m++)
                *(ull*)&out[(size_t)grow * 128 + 2 * tx + 32 * m] = acc[i][m];
        }
    }
}

// ---------------- CSR build -------------------------------------------------
__global__ void hist_k(const void* ei) {
    int e = blockIdx.x * blockDim.x + threadIdx.x;
    if (e >= ET) return;
    int d = (e < EE) ? get_edge(ei, 1, e) : (e - EE);
    atomicAdd(&g_deg[d], 1);
}

__global__ void scan1_k() {
    __shared__ int sm[1024];
    int t = threadIdx.x;
    int i = blockIdx.x * 1024 + t;
    int v = (i < NN) ? g_deg[i] : 0;
    sm[t] = v;
    __syncthreads();
    for (int off = 1; off < 1024; off <<= 1) {
        int u = (t >= off) ? sm[t - off] : 0;
        __syncthreads();
        sm[t] += u;
        __syncthreads();
    }
    if (i < NN) g_rowptr[i + 1] = sm[t];
    if (t == 1023) g_bsum[blockIdx.x] = sm[1023];
}

__global__ void scan2_k() {
    if (threadIdx.x == 0 && blockIdx.x == 0) {
        int run = 0;
        for (int i = 0; i < NSCAN_BLK; i++) { run += g_bsum[i]; g_bsum[i] = run; }
    }
}

__global__ void scan3_k() {
    int i = blockIdx.x * blockDim.x + threadIdx.x;
    if (i == 0) g_rowptr[0] = 0;
    if (i < NN) {
        int b = i >> 10;
        if (b > 0) g_rowptr[i + 1] += g_bsum[b - 1];
    }
}

__global__ void scatter_k(const void* ei) {
    int e = blockIdx.x * blockDim.x + threadIdx.x;
    if (e >= ET) return;
    int s, d;
    if (e < EE) { s = get_edge(ei, 0, e); d = get_edge(ei, 1, e); }
    else        { s = e - EE; d = e - EE; }
    int pos = g_rowptr[d] + atomicAdd(&g_cnt[d], 1);
    g_esrc[pos] = s;
    g_eid[pos]  = e;
}

// ---- conv1: warp/dst, online softmax (1 exp/head/edge), BN stats fused -----
__global__ void conv1_k(const float* __restrict__ att1, const float* __restrict__ b1,
                        float* __restrict__ out_alpha) {
    __shared__ float sbn[128], sbq[128];
    int tid = threadIdx.x;
    if (tid < 128) { sbn[tid] = 0.f; sbq[tid] = 0.f; }
    __syncthreads();
    int w = (blockIdx.x * blockDim.x + tid) >> 5;   // grid sized exactly: w < NN
    int l = tid & 31;
    const float* xrp = &g_xr1[(size_t)w * 128];
    float r0 = xrp[l], r1 = xrp[32 + l], r2 = xrp[64 + l], r3 = xrp[96 + l];
    float t0 = att1[l], t1 = att1[32 + l], t2 = att1[64 + l], t3 = att1[96 + l];
    float m0 = -1e30f, m1 = -1e30f, m2 = -1e30f, m3 = -1e30f;
    float s0 = 0.f, s1 = 0.f, s2 = 0.f, s3 = 0.f;
    float a0 = 0.f, a1 = 0.f, a2 = 0.f, a3 = 0.f;
    int beg = g_rowptr[w], end = g_rowptr[w + 1];   // deg >= 1 (self loop)
    int sn = g_esrc[beg];
    const float* xp0 = &g_xl1[(size_t)sn * 128];
    float c0 = xp0[l], c1 = xp0[32 + l], c2 = xp0[64 + l], c3 = xp0[96 + l];
    for (int i = beg; i < end; i++) {
        float n0 = c0, n1 = c1, n2 = c2, n3 = c3;
        if (i + 1 < end) {                           // prefetch next src row
            int s2i = g_esrc[i + 1];
            const float* np = &g_xl1[(size_t)s2i * 128];
            n0 = np[l]; n1 = np[32 + l]; n2 = np[64 + l]; n3 = np[96 + l];
        }
        float p0 = t0 * lrelu(c0 + r0, 0.2f);
        float p1 = t1 * lrelu(c1 + r1, 0.2f);
        float p2 = t2 * lrelu(c2 + r2, 0.2f);
        float p3 = t3 * lrelu(c3 + r3, 0.2f);
        // 15-shfl 4-head reduction
        p0 += __shfl_xor_sync(FULLMASK, p0, 16); p0 += __shfl_xor_sync(FULLMASK, p0, 8);
        p1 += __shfl_xor_sync(FULLMASK, p1, 16); p1 += __shfl_xor_sync(FULLMASK, p1, 8);
        p2 += __shfl_xor_sync(FULLMASK, p2, 16); p2 += __shfl_xor_sync(FULLMASK, p2, 8);
        p3 += __shfl_xor_sync(FULLMASK, p3, 16); p3 += __shfl_xor_sync(FULLMASK, p3, 8);
        float v = (l < 8) ? p0 : (l < 16) ? p1 : (l < 24) ? p2 : p3;
        v += __shfl_xor_sync(FULLMASK, v, 4);
        v += __shfl_xor_sync(FULLMASK, v, 2);
        v += __shfl_xor_sync(FULLMASK, v, 1);
        p0 = __shfl_sync(FULLMASK, v, 0);
        p1 = __shfl_sync(FULLMASK, v, 8);
        p2 = __shfl_sync(FULLMASK, v, 16);
        p3 = __shfl_sync(FULLMASK, v, 24);
        if (l == 0) *(float4*)&g_sc1[(size_t)i * 4] = make_float4(p0, p1, p2, p3);
        // single-exp online softmax (warp-uniform branches)
        float d;
        d = p0 - m0;
        if (d > 0.f) { float cc = __expf(-d); s0 = s0 * cc + 1.f; a0 = a0 * cc + c0; m0 = p0; }
        else         { float wt = __expf(d);  s0 += wt;           a0 += wt * c0; }
        d = p1 - m1;
        if (d > 0.f) { float cc = __expf(-d); s1 = s1 * cc + 1.f; a1 = a1 * cc + c1; m1 = p1; }
        else         { float wt = __expf(d);  s1 += wt;           a1 += wt * c1; }
        d = p2 - m2;
        if (d > 0.f) { float cc = __expf(-d); s2 = s2 * cc + 1.f; a2 = a2 * cc + c2; m2 = p2; }
        else         { float wt = __expf(d);  s2 += wt;           a2 += wt * c2; }
        d = p3 - m3;
        if (d > 0.f) { float cc = __expf(-d); s3 = s3 * cc + 1.f; a3 = a3 * cc + c3; m3 = p3; }
        else         { float wt = __expf(d);  s3 += wt;           a3 += wt * c3; }
        c0 = n0; c1 = n1; c2 = n2; c3 = n3;
    }
    float h0 = a0 / (s0 + 1e-16f) + b1[l];
    float h1 = a1 / (s1 + 1e-16f) + b1[32 + l];
    float h2 = a2 / (s2 + 1e-16f) + b1[64 + l];
    float h3 = a3 / (s3 + 1e-16f) + b1[96 + l];
    float* hp = &g_h1[(size_t)w * 128];
    hp[l] = h0; hp[32 + l] = h1; hp[64 + l] = h2; hp[96 + l] = h3;
    atomicAdd(&sbn[l], h0);       atomicAdd(&sbq[l], h0 * h0);
    atomicAdd(&sbn[32 + l], h1);  atomicAdd(&sbq[32 + l], h1 * h1);
    atomicAdd(&sbn[64 + l], h2);  atomicAdd(&sbq[64 + l], h2 * h2);
    atomicAdd(&sbn[96 + l], h3);  atomicAdd(&sbq[96 + l], h3 * h3);
    // alpha pass: 8 edges x 4 heads per iteration
    int hh = l & 3, eo = l >> 2;
    float mh = (hh == 0) ? m0 : (hh == 1) ? m1 : (hh == 2) ? m2 : m3;
    float sh = ((hh == 0) ? s0 : (hh == 1) ? s1 : (hh == 2) ? s2 : s3) + 1e-16f;
    float inv_sh = 1.f / sh;
    for (int i = beg + eo; i < end; i += 8) {
        float sc = g_sc1[(size_t)i * 4 + hh];
        int oe = g_eid[i];
        out_alpha[(size_t)oe * 4 + hh] = __expf(sc - mh) * inv_sh;
    }
    __syncthreads();
    if (tid < 128) {
        atomicAdd(&g_bnsum[tid], sbn[tid]);
        atomicAdd(&g_bnsq[tid],  sbq[tid]);
    }
}

__global__ void bnfin_k(const float* __restrict__ gamma, const float* __restrict__ beta) {
    int c = threadIdx.x;
    float mu = g_bnsum[c] * (1.f / NN);
    float var = g_bnsq[c] * (1.f / NN) - mu * mu;
    float sc = gamma[c] * rsqrtf(var + 1e-5f);
    g_bnscale[c] = sc;
    g_bnshift[c] = beta[c] - mu * sc;
}

// ---------------- GEMM 2: (BN+lrelu fused) xl2/xr2 = h1n @ [Wl2|Wr2] --------
__global__ __launch_bounds__(256, 2) void gemm2_k(const float* __restrict__ Wl2,
                                                  const float* __restrict__ Wr2) {
    __shared__ float Ast[32][130];
    __shared__ float Bs[32][68];
    int rowbase = blockIdx.x * 128;
    int tid = threadIdx.x;
    int tx = tid & 15, ty = tid >> 4;
    ull acc[8][2];
#pragma unroll
    for (int i = 0; i < 8; i++) { acc[i][0] = 0ull; acc[i][1] = 0ull; }

    for (int kb = 0; kb < 128; kb += 32) {
#pragma unroll
        for (int p = 0; p < 4; p++) {                 // A: BN + lrelu on load
            int lin = p * 1024 + tid * 4;
            int r = lin >> 5, kkb = lin & 31;
            int grow = rowbase + r;
            float4 v = make_float4(0.f, 0.f, 0.f, 0.f);
            if (grow < NN) {
                v = *(const float4*)&g_h1[(size_t)grow * 128 + kb + kkb];
                int c = kb + kkb;
                v.x = lrelu(v.x * g_bnscale[c]     + g_bnshift[c],     0.01f);
                v.y = lrelu(v.y * g_bnscale[c + 1] + g_bnshift[c + 1], 0.01f);
                v.z = lrelu(v.z * g_bnscale[c + 2] + g_bnshift[c + 2], 0.01f);
                v.w = lrelu(v.w * g_bnscale[c + 3] + g_bnshift[c + 3], 0.01f);
            }
            Ast[kkb + 0][r] = v.x; Ast[kkb + 1][r] = v.y;
            Ast[kkb + 2][r] = v.z; Ast[kkb + 3][r] = v.w;
        }
#pragma unroll
        for (int p = 0; p < 2; p++) {                 // B: 32 k x 64 cols
            int lin = p * 1024 + tid * 4;
            int kk = lin >> 6, c = lin & 63;
            float4 v;
            if (c < 32) v = *(const float4*)&Wl2[(size_t)(kb + kk) * 32 + c];
            else        v = *(const float4*)&Wr2[(size_t)(kb + kk) * 32 + (c - 32)];
            *(float4*)&Bs[kk][c] = v;
        }
        __syncthreads();
#pragma unroll 8
        for (int kk = 0; kk < 32; kk++) {
            ull bv0 = *(ull*)&Bs[kk][2 * tx];
            ull bv1 = *(ull*)&Bs[kk][2 * tx + 32];
#pragma unroll
            for (int rp = 0; rp < 4; rp++) {
                float a0, a1;
                unpack2(*(ull*)&Ast[kk][ty * 8 + 2 * rp], a0, a1);
                ull d0 = pack2(a0, a0), d1 = pack2(a1, a1);
                acc[2 * rp][0]     = fma2(d0, bv0, acc[2 * rp][0]);
                acc[2 * rp][1]     = fma2(d0, bv1, acc[2 * rp][1]);
                acc[2 * rp + 1][0] = fma2(d1, bv0, acc[2 * rp + 1][0]);
                acc[2 * rp + 1][1] = fma2(d1, bv1, acc[2 * rp + 1][1]);
            }
        }
        __syncthreads();
    }
#pragma unroll
    for (int i = 0; i < 8; i++) {
        int grow = rowbase + ty * 8 + i;
        if (grow < NN) {
            *(ull*)&g_xl2[(size_t)grow * 32 + 2 * tx] = acc[i][0];
            *(ull*)&g_xr2[(size_t)grow * 32 + 2 * tx] = acc[i][1];
        }
    }
}

// ---------------- conv2 + leaky + Wout + log_softmax ------------------------
__global__ void conv2_k(const float* __restrict__ att2, const float* __restrict__ b2,
                        const float* __restrict__ Wout, const float* __restrict__ bout,
                        float* __restrict__ out_logp) {
    int w = (blockIdx.x * blockDim.x + threadIdx.x) >> 5;   // grid exact: w < NN
    int l = threadIdx.x & 31;
    float xr = g_xr2[(size_t)w * 32 + l];
    float at = att2[l];
    float m = -1e30f, s = 0.f, a = 0.f;
    int beg = g_rowptr[w], end = g_rowptr[w + 1];
    float cx = g_xl2[(size_t)g_esrc[beg] * 32 + l];
    for (int i = beg; i < end; i++) {
        float nx = cx;
        if (i + 1 < end) nx = g_xl2[(size_t)g_esrc[i + 1] * 32 + l];
        float p = at * lrelu(cx + xr, 0.2f);
        p = wred(p);
        float d = p - m;
        if (d > 0.f) { float cc = __expf(-d); s = s * cc + 1.f; a = a * cc + cx; m = p; }
        else         { float wt = __expf(d);  s += wt;          a += wt * cx; }
        cx = nx;
    }
    float h = a / (s + 1e-16f) + b2[l];
    h = lrelu(h, 0.01f);
    float q0 = h * Wout[l * 3 + 0];
    float q1 = h * Wout[l * 3 + 1];
    float q2 = h * Wout[l * 3 + 2];
    q0 = wred(q0) + bout[0];
    q1 = wred(q1) + bout[1];
    q2 = wred(q2) + bout[2];
    float mx = fmaxf(q0, fmaxf(q1, q2));
    float lse = logf(expf(q0 - mx) + expf(q1 - mx) + expf(q2 - mx)) + mx;
    if (l < 3) {
        float z = (l == 0) ? q0 : (l == 1) ? q1 : q2;
        out_logp[(size_t)w * 3 + l] = z - lse;
    }
}

// ---------------- launcher --------------------------------------------------
extern "C" void kernel_launch(void* const* d_in, const int* in_sizes, int n_in,
                              void* d_out, int out_size) {
    const float* x     = (const float*)d_in[0];
    const void*  ei    = d_in[1];
    const float* Wl1   = (const float*)d_in[2];
    const float* Wr1   = (const float*)d_in[3];
    const float* att1  = (const float*)d_in[4];
    const float* b1    = (const float*)d_in[5];
    const float* gamma = (const float*)d_in[6];
    const float* beta  = (const float*)d_in[7];
    const float* Wl2   = (const float*)d_in[8];
    const float* Wr2   = (const float*)d_in[9];
    const float* att2  = (const float*)d_in[10];
    const float* b2    = (const float*)d_in[11];
    const float* Wout  = (const float*)d_in[12];
    const float* bout  = (const float*)d_in[13];
    float* out       = (float*)d_out;
    float* out_logp  = out;
    float* out_alpha = out + (size_t)NN * 3;

    init_k<<<(NN + 255) / 256, 256>>>((const int*)ei);
    gemm1_k<<<dim3((NN + 127) / 128, 2), 256>>>(x, Wl1, Wr1);
    hist_k<<<(ET + 255) / 256, 256>>>(ei);
    scan1_k<<<NSCAN_BLK, 1024>>>();
    scan2_k<<<1, 32>>>();
    scan3_k<<<(NN + 255) / 256, 256>>>();
    scatter_k<<<(ET + 255) / 256, 256>>>(ei);
    conv1_k<<<NN / 8, 256>>>(att1, b1, out_alpha);
    bnfin_k<<<1, 128>>>(gamma, beta);
    gemm2_k<<<(NN + 127) / 128, 256>>>(Wl2, Wr2);
    conv2_k<<<NN / 8, 256>>>(att2, b2, Wout, bout, out_logp);
}

// round 5
// speedup vs baseline: 1.6008x; 1.2167x over previous
#include <cuda_runtime.h>

#define NN 100000
#define EE 1600000
#define ET 1700000            // EE + NN self loops
#define NSCAN_BLK 98          // ceil(NN/1024)
#define FULLMASK 0xffffffffu

typedef unsigned long long ull;

// ---------------- scratch (static device globals: no runtime allocation) ----
__device__ float g_xl1[NN * 128];
__device__ float g_xr1[NN * 128];
__device__ float g_h1 [NN * 128];
__device__ float g_xl2[NN * 32];
__device__ float g_xr2[NN * 32];
__device__ float g_sc1[ET * 4];        // layer-1 scores in CSR order
__device__ int   g_deg[NN];
__device__ int   g_cnt[NN];
__device__ int   g_rowptr[NN + 1];
__device__ int   g_esrc[ET];
__device__ int   g_eid [ET];
__device__ int   g_bsum[NSCAN_BLK];
__device__ float g_bnsum[128], g_bnsq[128];
__device__ float g_bnscale[128], g_bnshift[128];
__device__ int   g_is64;

// ---------------- helpers ---------------------------------------------------
__device__ __forceinline__ ull fma2(ull a, ull b, ull c) {
    ull d; asm("fma.rn.f32x2 %0, %1, %2, %3;" : "=l"(d) : "l"(a), "l"(b), "l"(c)); return d;
}
__device__ __forceinline__ ull pack2(float lo, float hi) {
    ull r; asm("mov.b64 %0, {%1, %2};" : "=l"(r) : "f"(lo), "f"(hi)); return r;
}
__device__ __forceinline__ void unpack2(ull v, float& lo, float& hi) {
    asm("mov.b64 {%0, %1}, %2;" : "=f"(lo), "=f"(hi) : "l"(v));
}
__device__ __forceinline__ float lrelu(float v, float s) { return v > 0.f ? v : s * v; }

__device__ __forceinline__ int get_edge(const void* ei, int which, int e) {
    if (g_is64) return (int)((const long long*)ei)[(size_t)which * EE + e];
    return ((const int*)ei)[(size_t)which * EE + e];
}

// init + edge-index dtype probe (int64 nonneg -> every odd 32-bit word is 0)
__global__ void init_k(const int* ei) {
    int i = blockIdx.x * blockDim.x + threadIdx.x;
    if (i < NN) { g_deg[i] = 0; g_cnt[i] = 0; }
    if (i < 128) { g_bnsum[i] = 0.f; g_bnsq[i] = 0.f; }
    if (i == 0) {
        int z = 1;
        for (int k = 1; k < 129; k += 2) if (ei[k] != 0) { z = 0; break; }
        g_is64 = z;
    }
}

// ---------------- GEMM 1: xl1 = x@Wl1, xr1 = x@Wr1 (f32x2, 128x128 tiles) ---
__global__ __launch_bounds__(256, 2) void gemm1_k(const float* __restrict__ x,
                                                  const float* __restrict__ Wl,
                                                  const float* __restrict__ Wr) {
    __shared__ float Ast[32][130];   // A tile transposed [k][row]
    __shared__ float Bs[32][132];    // B tile [k][col]
    const float* W = blockIdx.y ? Wr : Wl;
    float* out = blockIdx.y ? g_xr1 : g_xl1;
    int rowbase = blockIdx.x * 128;
    int tid = threadIdx.x;
    int tx = tid & 15, ty = tid >> 4;
    ull acc[8][4];
#pragma unroll
    for (int i = 0; i < 8; i++)
#pragma unroll
        for (int m = 0; m < 4; m++) acc[i][m] = 0ull;

    for (int kb = 0; kb < 128; kb += 32) {
#pragma unroll
        for (int p = 0; p < 4; p++) {                 // A: 128 rows x 32 k
            int lin = p * 1024 + tid * 4;
            int r = lin >> 5, kkb = lin & 31;
            int grow = rowbase + r;
            float4 v = make_float4(0.f, 0.f, 0.f, 0.f);
            if (grow < NN) v = *(const float4*)&x[(size_t)grow * 128 + kb + kkb];
            Ast[kkb + 0][r] = v.x; Ast[kkb + 1][r] = v.y;
            Ast[kkb + 2][r] = v.z; Ast[kkb + 3][r] = v.w;
        }
#pragma unroll
        for (int p = 0; p < 4; p++) {                 // B: 32 k x 128 cols
            int lin = p * 1024 + tid * 4;
            int kk = lin >> 7, c = lin & 127;
            *(float4*)&Bs[kk][c] = *(const float4*)&W[(size_t)(kb + kk) * 128 + c];
        }
        __syncthreads();
#pragma unroll 8
        for (int kk = 0; kk < 32; kk++) {
            ull bv[4];
#pragma unroll
            for (int m = 0; m < 4; m++) bv[m] = *(ull*)&Bs[kk][2 * tx + 32 * m];
#pragma unroll
            for (int rp = 0; rp < 4; rp++) {
                float a0, a1;
                unpack2(*(ull*)&Ast[kk][ty * 8 + 2 * rp], a0, a1);
                ull d0 = pack2(a0, a0), d1 = pack2(a1, a1);
#pragma unroll
                for (int m = 0; m < 4; m++) {
                    acc[2 * rp][m]     = fma2(d0, bv[m], acc[2 * rp][m]);
                    acc[2 * rp + 1][m] = fma2(d1, bv[m], acc[2 * rp + 1][m]);
                }
            }
        }
        __syncthreads();
    }
#pragma unroll
    for (int i = 0; i < 8; i++) {
        int grow = rowbase + ty * 8 + i;
        if (grow < NN) {
#pragma unroll
            for (int m = 0; m < 4; m++)
                *(ull*)&out[(size_t)grow * 128 + 2 * tx + 32 * m] = acc[i][m];
        }
    }
}

// ---------------- CSR build -------------------------------------------------
__global__ void hist_k(const void* ei) {
    int e = blockIdx.x * blockDim.x + threadIdx.x;
    if (e >= ET) return;
    int d = (e < EE) ? get_edge(ei, 1, e) : (e - EE);
    atomicAdd(&g_deg[d], 1);
}

__global__ void scan1_k() {
    __shared__ int sm[1024];
    int t = threadIdx.x;
    int i = blockIdx.x * 1024 + t;
    int v = (i < NN) ? g_deg[i] : 0;
    sm[t] = v;
    __syncthreads();
    for (int off = 1; off < 1024; off <<= 1) {
        int u = (t >= off) ? sm[t - off] : 0;
        __syncthreads();
        sm[t] += u;
        __syncthreads();
    }
    if (i < NN) g_rowptr[i + 1] = sm[t];
    if (t == 1023) g_bsum[blockIdx.x] = sm[1023];
}

__global__ void scan2_k() {
    if (threadIdx.x == 0 && blockIdx.x == 0) {
        int run = 0;
        for (int i = 0; i < NSCAN_BLK; i++) { run += g_bsum[i]; g_bsum[i] = run; }
    }
}

__global__ void scan3_k() {
    int i = blockIdx.x * blockDim.x + threadIdx.x;
    if (i == 0) g_rowptr[0] = 0;
    if (i < NN) {
        int b = i >> 10;
        if (b > 0) g_rowptr[i + 1] += g_bsum[b - 1];
    }
}

__global__ void scatter_k(const void* ei) {
    int e = blockIdx.x * blockDim.x + threadIdx.x;
    if (e >= ET) return;
    int s, d;
    if (e < EE) { s = get_edge(ei, 0, e); d = get_edge(ei, 1, e); }
    else        { s = e - EE; d = e - EE; }
    int pos = g_rowptr[d] + atomicAdd(&g_cnt[d], 1);
    g_esrc[pos] = s;
    g_eid[pos]  = e;
}

// ---- conv1: warp/dst, lane = 4 channels, head = 8-lane group ---------------
// per edge: 1 LDG.128/lane, 3 SHFL, 1 MUFU, branchless online softmax.
__global__ void conv1_k(const float* __restrict__ att1, const float* __restrict__ b1,
                        float* __restrict__ out_alpha) {
    __shared__ float sbn[128], sbq[128];
    int tid = threadIdx.x;
    if (tid < 128) { sbn[tid] = 0.f; sbq[tid] = 0.f; }
    __syncthreads();
    int w = (blockIdx.x * blockDim.x + tid) >> 5;   // grid exact: w < NN
    int l = tid & 31;
    int ch = 4 * l;                                  // channel base; head = l>>3
    float4 rr = *(const float4*)&g_xr1[(size_t)w * 128 + ch];
    float4 tt = *(const float4*)&att1[ch];
    float m = -1e30f, s = 0.f;
    float4 a = make_float4(0.f, 0.f, 0.f, 0.f);
    int beg = g_rowptr[w], end = g_rowptr[w + 1];   // deg >= 1 (self loop)
    float4 c = *(const float4*)&g_xl1[(size_t)g_esrc[beg] * 128 + ch];
    for (int i = beg; i < end; i++) {
        float4 n = c;
        if (i + 1 < end)
            n = *(const float4*)&g_xl1[(size_t)g_esrc[i + 1] * 128 + ch];
        float p = tt.x * lrelu(c.x + rr.x, 0.2f);
        p = fmaf(tt.y, lrelu(c.y + rr.y, 0.2f), p);
        p = fmaf(tt.z, lrelu(c.z + rr.z, 0.2f), p);
        p = fmaf(tt.w, lrelu(c.w + rr.w, 0.2f), p);
        p += __shfl_xor_sync(FULLMASK, p, 4);
        p += __shfl_xor_sync(FULLMASK, p, 2);
        p += __shfl_xor_sync(FULLMASK, p, 1);        // all 4 heads reduced in-group
        if ((l & 7) == 0) g_sc1[(size_t)i * 4 + (l >> 3)] = p;
        // branchless single-exp online softmax
        float d = p - m;
        bool pos = d > 0.f;
        float e = __expf(-fabsf(d));
        float sm = pos ? e : 1.f;
        float wn = pos ? 1.f : e;
        s = s * sm + wn;
        a.x = a.x * sm + wn * c.x;
        a.y = a.y * sm + wn * c.y;
        a.z = a.z * sm + wn * c.z;
        a.w = a.w * sm + wn * c.w;
        m = fmaxf(m, p);
        c = n;
    }
    float inv = 1.f / (s + 1e-16f);
    float4 bb = *(const float4*)&b1[ch];
    float4 h;
    h.x = a.x * inv + bb.x; h.y = a.y * inv + bb.y;
    h.z = a.z * inv + bb.z; h.w = a.w * inv + bb.w;
    *(float4*)&g_h1[(size_t)w * 128 + ch] = h;
    atomicAdd(&sbn[ch],     h.x); atomicAdd(&sbq[ch],     h.x * h.x);
    atomicAdd(&sbn[ch + 1], h.y); atomicAdd(&sbq[ch + 1], h.y * h.y);
    atomicAdd(&sbn[ch + 2], h.z); atomicAdd(&sbq[ch + 2], h.z * h.z);
    atomicAdd(&sbn[ch + 3], h.w); atomicAdd(&sbq[ch + 3], h.w * h.w);
    // alpha pass: head hh = l&3 state lives in lane 8*hh
    int hh = l & 3, eo = l >> 2;
    float mh   = __shfl_sync(FULLMASK, m,   hh << 3);
    float invh = __shfl_sync(FULLMASK, inv, hh << 3);
    for (int i = beg + eo; i < end; i += 8) {
        float sc = g_sc1[(size_t)i * 4 + hh];
        int oe = g_eid[i];
        out_alpha[(size_t)oe * 4 + hh] = __expf(sc - mh) * invh;
    }
    __syncthreads();
    if (tid < 128) {
        atomicAdd(&g_bnsum[tid], sbn[tid]);
        atomicAdd(&g_bnsq[tid],  sbq[tid]);
    }
}

__global__ void bnfin_k(const float* __restrict__ gamma, const float* __restrict__ beta) {
    int c = threadIdx.x;
    float mu = g_bnsum[c] * (1.f / NN);
    float var = g_bnsq[c] * (1.f / NN) - mu * mu;
    float sc = gamma[c] * rsqrtf(var + 1e-5f);
    g_bnscale[c] = sc;
    g_bnshift[c] = beta[c] - mu * sc;
}

// ---------------- GEMM 2: (BN+lrelu fused) xl2/xr2 = h1n @ [Wl2|Wr2] --------
__global__ __launch_bounds__(256, 2) void gemm2_k(const float* __restrict__ Wl2,
                                                  const float* __restrict__ Wr2) {
    __shared__ float Ast[32][130];
    __shared__ float Bs[32][68];
    int rowbase = blockIdx.x * 128;
    int tid = threadIdx.x;
    int tx = tid & 15, ty = tid >> 4;
    ull acc[8][2];
#pragma unroll
    for (int i = 0; i < 8; i++) { acc[i][0] = 0ull; acc[i][1] = 0ull; }

    for (int kb = 0; kb < 128; kb += 32) {
#pragma unroll
        for (int p = 0; p < 4; p++) {                 // A: BN + lrelu on load
            int lin = p * 1024 + tid * 4;
            int r = lin >> 5, kkb = lin & 31;
            int grow = rowbase + r;
            float4 v = make_float4(0.f, 0.f, 0.f, 0.f);
            if (grow < NN) {
                v = *(const float4*)&g_h1[(size_t)grow * 128 + kb + kkb];
                int c = kb + kkb;
                v.x = lrelu(v.x * g_bnscale[c]     + g_bnshift[c],     0.01f);
                v.y = lrelu(v.y * g_bnscale[c + 1] + g_bnshift[c + 1], 0.01f);
                v.z = lrelu(v.z * g_bnscale[c + 2] + g_bnshift[c + 2], 0.01f);
                v.w = lrelu(v.w * g_bnscale[c + 3] + g_bnshift[c + 3], 0.01f);
            }
            Ast[kkb + 0][r] = v.x; Ast[kkb + 1][r] = v.y;
            Ast[kkb + 2][r] = v.z; Ast[kkb + 3][r] = v.w;
        }
#pragma unroll
        for (int p = 0; p < 2; p++) {                 // B: 32 k x 64 cols
            int lin = p * 1024 + tid * 4;
            int kk = lin >> 6, c = lin & 63;
            float4 v;
            if (c < 32) v = *(const float4*)&Wl2[(size_t)(kb + kk) * 32 + c];
            else        v = *(const float4*)&Wr2[(size_t)(kb + kk) * 32 + (c - 32)];
            *(float4*)&Bs[kk][c] = v;
        }
        __syncthreads();
#pragma unroll 8
        for (int kk = 0; kk < 32; kk++) {
            ull bv0 = *(ull*)&Bs[kk][2 * tx];
            ull bv1 = *(ull*)&Bs[kk][2 * tx + 32];
#pragma unroll
            for (int rp = 0; rp < 4; rp++) {
                float a0, a1;
                unpack2(*(ull*)&Ast[kk][ty * 8 + 2 * rp], a0, a1);
                ull d0 = pack2(a0, a0), d1 = pack2(a1, a1);
                acc[2 * rp][0]     = fma2(d0, bv0, acc[2 * rp][0]);
                acc[2 * rp][1]     = fma2(d0, bv1, acc[2 * rp][1]);
                acc[2 * rp + 1][0] = fma2(d1, bv0, acc[2 * rp + 1][0]);
                acc[2 * rp + 1][1] = fma2(d1, bv1, acc[2 * rp + 1][1]);
            }
        }
        __syncthreads();
    }
#pragma unroll
    for (int i = 0; i < 8; i++) {
        int grow = rowbase + ty * 8 + i;
        if (grow < NN) {
            *(ull*)&g_xl2[(size_t)grow * 32 + 2 * tx] = acc[i][0];
            *(ull*)&g_xr2[(size_t)grow * 32 + 2 * tx] = acc[i][1];
        }
    }
}

// ---- conv2: 2 dst nodes per warp (16-lane groups, 2 channels/lane) ---------
__global__ void conv2_k(const float* __restrict__ att2, const float* __restrict__ b2,
                        const float* __restrict__ Wout, const float* __restrict__ bout,
                        float* __restrict__ out_logp) {
    int warp = (blockIdx.x * blockDim.x + threadIdx.x) >> 5;  // warp < NN/2
    int l = threadIdx.x & 31;
    int g = l >> 4, lg = l & 15;
    int w = 2 * warp + g;
    int ch = 2 * lg;
    float2 xr = *(const float2*)&g_xr2[(size_t)w * 32 + ch];
    float2 at = *(const float2*)&att2[ch];
    float m = -1e30f, s = 0.f;
    float2 a = make_float2(0.f, 0.f);
    int beg = g_rowptr[w], end = g_rowptr[w + 1];
    int deg = end - beg;                               // >= 1
    int mx = max(deg, __shfl_xor_sync(FULLMASK, deg, 16));
    float2 c = *(const float2*)&g_xl2[(size_t)g_esrc[beg] * 32 + ch];
    for (int k = 0; k < mx; k++) {
        bool act = k < deg;
        float2 n = c;
        if (k + 1 < deg)
            n = *(const float2*)&g_xl2[(size_t)g_esrc[beg + k + 1] * 32 + ch];
        float p = at.x * lrelu(c.x + xr.x, 0.2f);
        p = fmaf(at.y, lrelu(c.y + xr.y, 0.2f), p);
        p += __shfl_xor_sync(FULLMASK, p, 8);
        p += __shfl_xor_sync(FULLMASK, p, 4);
        p += __shfl_xor_sync(FULLMASK, p, 2);
        p += __shfl_xor_sync(FULLMASK, p, 1);
        float d = p - m;
        bool pos = (d > 0.f) && act;
        float e = __expf(-fabsf(d));
        float sm = pos ? e : 1.f;
        float wn = act ? (pos ? 1.f : e) : 0.f;
        s = s * sm + wn;
        a.x = a.x * sm + wn * c.x;
        a.y = a.y * sm + wn * c.y;
        m = pos ? p : m;
        c = n;
    }
    float inv = 1.f / (s + 1e-16f);
    float2 bb = *(const float2*)&b2[ch];
    float hx = lrelu(a.x * inv + bb.x, 0.01f);
    float hy = lrelu(a.y * inv + bb.y, 0.01f);
    float q0 = hx * Wout[ch * 3 + 0] + hy * Wout[(ch + 1) * 3 + 0];
    float q1 = hx * Wout[ch * 3 + 1] + hy * Wout[(ch + 1) * 3 + 1];
    float q2 = hx * Wout[ch * 3 + 2] + hy * Wout[(ch + 1) * 3 + 2];
#pragma unroll
    for (int off = 8; off >= 1; off >>= 1) {
        q0 += __shfl_xor_sync(FULLMASK, q0, off);
        q1 += __shfl_xor_sync(FULLMASK, q1, off);
        q2 += __shfl_xor_sync(FULLMASK, q2, off);
    }
    q0 += bout[0]; q1 += bout[1]; q2 += bout[2];
    float mxq = fmaxf(q0, fmaxf(q1, q2));
    float lse = logf(expf(q0 - mxq) + expf(q1 - mxq) + expf(q2 - mxq)) + mxq;
    if (lg < 3) {
        float z = (lg == 0) ? q0 : (lg == 1) ? q1 : q2;
        out_logp[(size_t)w * 3 + lg] = z - lse;
    }
}

// ---------------- launcher --------------------------------------------------
extern "C" void kernel_launch(void* const* d_in, const int* in_sizes, int n_in,
                              void* d_out, int out_size) {
    const float* x     = (const float*)d_in[0];
    const void*  ei    = d_in[1];
    const float* Wl1   = (const float*)d_in[2];
    const float* Wr1   = (const float*)d_in[3];
    const float* att1  = (const float*)d_in[4];
    const float* b1    = (const float*)d_in[5];
    const float* gamma = (const float*)d_in[6];
    const float* beta  = (const float*)d_in[7];
    const float* Wl2   = (const float*)d_in[8];
    const float* Wr2   = (const float*)d_in[9];
    const float* att2  = (const float*)d_in[10];
    const float* b2    = (const float*)d_in[11];
    const float* Wout  = (const float*)d_in[12];
    const float* bout  = (const float*)d_in[13];
    float* out       = (float*)d_out;
    float* out_logp  = out;
    float* out_alpha = out + (size_t)NN * 3;

    init_k<<<(NN + 255) / 256, 256>>>((const int*)ei);
    gemm1_k<<<dim3((NN + 127) / 128, 2), 256>>>(x, Wl1, Wr1);
    hist_k<<<(ET + 255) / 256, 256>>>(ei);
    scan1_k<<<NSCAN_BLK, 1024>>>();
    scan2_k<<<1, 32>>>();
    scan3_k<<<(NN + 255) / 256, 256>>>();
    scatter_k<<<(ET + 255) / 256, 256>>>(ei);
    conv1_k<<<NN / 8, 256>>>(att1, b1, out_alpha);
    bnfin_k<<<1, 128>>>(gamma, beta);
    gemm2_k<<<(NN + 127) / 128, 256>>>(Wl2, Wr2);
    conv2_k<<<NN / 16, 256>>>(att2, b2, Wout, bout, out_logp);
}

// round 6
// speedup vs baseline: 1.6081x; 1.0046x over previous
#include <cuda_runtime.h>

#define NN 100000
#define EE 1600000
#define ET 1700000            // EE + NN self loops
#define NSCAN_BLK 98          // ceil(NN/1024)
#define FULLMASK 0xffffffffu

typedef unsigned long long ull;

// ---------------- scratch (static device globals: no runtime allocation) ----
__device__ float g_xl1[NN * 128];
__device__ float g_xr1[NN * 128];
__device__ float g_h1 [NN * 128];
__device__ float g_xl2[NN * 32];
__device__ float g_xr2[NN * 32];
__device__ float g_m1 [NN * 4];        // per-node per-head running max
__device__ float g_inv1[NN * 4];       // per-node per-head 1/sum
__device__ int   g_deg[NN];
__device__ int   g_cnt[NN];
__device__ int   g_rowptr[NN + 1];
__device__ int   g_esrc[ET];
__device__ int   g_eid [ET];
__device__ int   g_bsum[NSCAN_BLK];
__device__ float g_bnsum[128], g_bnsq[128];
__device__ float g_bnscale[128], g_bnshift[128];
__device__ int   g_is64;

// ---------------- helpers ---------------------------------------------------
__device__ __forceinline__ ull fma2(ull a, ull b, ull c) {
    ull d; asm("fma.rn.f32x2 %0, %1, %2, %3;" : "=l"(d) : "l"(a), "l"(b), "l"(c)); return d;
}
__device__ __forceinline__ ull pack2(float lo, float hi) {
    ull r; asm("mov.b64 %0, {%1, %2};" : "=l"(r) : "f"(lo), "f"(hi)); return r;
}
__device__ __forceinline__ void unpack2(ull v, float& lo, float& hi) {
    asm("mov.b64 {%0, %1}, %2;" : "=f"(lo), "=f"(hi) : "l"(v));
}
__device__ __forceinline__ float lrelu(float v, float s) { return v > 0.f ? v : s * v; }

__device__ __forceinline__ int get_edge(const void* ei, int which, int e) {
    if (g_is64) return (int)((const long long*)ei)[(size_t)which * EE + e];
    return ((const int*)ei)[(size_t)which * EE + e];
}

// init + edge-index dtype probe (int64 nonneg -> every odd 32-bit word is 0)
__global__ void init_k(const int* ei) {
    int i = blockIdx.x * blockDim.x + threadIdx.x;
    if (i < NN) { g_deg[i] = 0; g_cnt[i] = 0; }
    if (i < 128) { g_bnsum[i] = 0.f; g_bnsq[i] = 0.f; }
    if (i == 0) {
        int z = 1;
        for (int k = 1; k < 129; k += 2) if (ei[k] != 0) { z = 0; break; }
        g_is64 = z;
    }
}

// ---------------- GEMM 1: xl1 = x@Wl1, xr1 = x@Wr1 (f32x2, 128x128 tiles) ---
__global__ __launch_bounds__(256, 2) void gemm1_k(const float* __restrict__ x,
                                                  const float* __restrict__ Wl,
                                                  const float* __restrict__ Wr) {
    __shared__ float Ast[32][130];   // A tile transposed [k][row]
    __shared__ float Bs[32][132];    // B tile [k][col]
    const float* W = blockIdx.y ? Wr : Wl;
    float* out = blockIdx.y ? g_xr1 : g_xl1;
    int rowbase = blockIdx.x * 128;
    int tid = threadIdx.x;
    int tx = tid & 15, ty = tid >> 4;
    ull acc[8][4];
#pragma unroll
    for (int i = 0; i < 8; i++)
#pragma unroll
        for (int m = 0; m < 4; m++) acc[i][m] = 0ull;

    for (int kb = 0; kb < 128; kb += 32) {
#pragma unroll
        for (int p = 0; p < 4; p++) {                 // A: 128 rows x 32 k
            int lin = p * 1024 + tid * 4;
            int r = lin >> 5, kkb = lin & 31;
            int grow = rowbase + r;
            float4 v = make_float4(0.f, 0.f, 0.f, 0.f);
            if (grow < NN) v = *(const float4*)&x[(size_t)grow * 128 + kb + kkb];
            Ast[kkb + 0][r] = v.x; Ast[kkb + 1][r] = v.y;
            Ast[kkb + 2][r] = v.z; Ast[kkb + 3][r] = v.w;
        }
#pragma unroll
        for (int p = 0; p < 4; p++) {                 // B: 32 k x 128 cols
            int lin = p * 1024 + tid * 4;
            int kk = lin >> 7, c = lin & 127;
            *(float4*)&Bs[kk][c] = *(const float4*)&W[(size_t)(kb + kk) * 128 + c];
        }
        __syncthreads();
#pragma unroll 8
        for (int kk = 0; kk < 32; kk++) {
            ull bv[4];
#pragma unroll
            for (int m = 0; m < 4; m++) bv[m] = *(ull*)&Bs[kk][2 * tx + 32 * m];
#pragma unroll
            for (int rp = 0; rp < 4; rp++) {
                float a0, a1;
                unpack2(*(ull*)&Ast[kk][ty * 8 + 2 * rp], a0, a1);
                ull d0 = pack2(a0, a0), d1 = pack2(a1, a1);
#pragma unroll
                for (int m = 0; m < 4; m++) {
                    acc[2 * rp][m]     = fma2(d0, bv[m], acc[2 * rp][m]);
                    acc[2 * rp + 1][m] = fma2(d1, bv[m], acc[2 * rp + 1][m]);
                }
            }
        }
        __syncthreads();
    }
#pragma unroll
    for (int i = 0; i < 8; i++) {
        int grow = rowbase + ty * 8 + i;
        if (grow < NN) {
#pragma unroll
            for (int m = 0; m < 4; m++)
                *(ull*)&out[(size_t)grow * 128 + 2 * tx + 32 * m] = acc[i][m];
        }
    }
}

// ---------------- CSR build -------------------------------------------------
__global__ void hist_k(const void* ei) {
    int e = blockIdx.x * blockDim.x + threadIdx.x;
    if (e >= ET) return;
    int d = (e < EE) ? get_edge(ei, 1, e) : (e - EE);
    atomicAdd(&g_deg[d], 1);
}

__global__ void scan1_k() {
    __shared__ int sm[1024];
    int t = threadIdx.x;
    int i = blockIdx.x * 1024 + t;
    int v = (i < NN) ? g_deg[i] : 0;
    sm[t] = v;
    __syncthreads();
    for (int off = 1; off < 1024; off <<= 1) {
        int u = (t >= off) ? sm[t - off] : 0;
        __syncthreads();
        sm[t] += u;
        __syncthreads();
    }
    if (i < NN) g_rowptr[i + 1] = sm[t];
    if (t == 1023) g_bsum[blockIdx.x] = sm[1023];
}

__global__ void scan2_k() {
    if (threadIdx.x == 0 && blockIdx.x == 0) {
        int run = 0;
        for (int i = 0; i < NSCAN_BLK; i++) { run += g_bsum[i]; g_bsum[i] = run; }
    }
}

__global__ void scan3_k() {
    int i = blockIdx.x * blockDim.x + threadIdx.x;
    if (i == 0) g_rowptr[0] = 0;
    if (i < NN) {
        int b = i >> 10;
        if (b > 0) g_rowptr[i + 1] += g_bsum[b - 1];
    }
}

__global__ void scatter_k(const void* ei) {
    int e = blockIdx.x * blockDim.x + threadIdx.x;
    if (e >= ET) return;
    int s, d;
    if (e < EE) { s = get_edge(ei, 0, e); d = get_edge(ei, 1, e); }
    else        { s = e - EE; d = e - EE; }
    int pos = g_rowptr[d] + atomicAdd(&g_cnt[d], 1);
    g_esrc[pos] = s;
    g_eid[pos]  = e;
}

// ---- conv1: warp/dst, lane = 4 channels, head = 8-lane group ---------------
// per edge: 1 LDG.128/lane, 3 SHFL, 1 MUFU, branchless online softmax.
// Raw scores scattered to out_alpha[eid]; alpha_fix_k normalizes later.
__global__ void conv1_k(const float* __restrict__ att1, const float* __restrict__ b1,
                        float* __restrict__ out_alpha) {
    __shared__ float sbn[128], sbq[128];
    int tid = threadIdx.x;
    if (tid < 128) { sbn[tid] = 0.f; sbq[tid] = 0.f; }
    __syncthreads();
    int w = (blockIdx.x * blockDim.x + tid) >> 5;   // grid exact: w < NN
    int l = tid & 31;
    int ch = 4 * l;                                  // channel base; head = l>>3
    float4 rr = *(const float4*)&g_xr1[(size_t)w * 128 + ch];
    float4 tt = *(const float4*)&att1[ch];
    float m = -1e30f, s = 0.f;
    float4 a = make_float4(0.f, 0.f, 0.f, 0.f);
    int beg = g_rowptr[w], end = g_rowptr[w + 1];   // deg >= 1 (self loop)
    float4 c = *(const float4*)&g_xl1[(size_t)g_esrc[beg] * 128 + ch];
    for (int i = beg; i < end; i++) {
        float4 n = c;
        if (i + 1 < end)
            n = *(const float4*)&g_xl1[(size_t)g_esrc[i + 1] * 128 + ch];
        float p = tt.x * lrelu(c.x + rr.x, 0.2f);
        p = fmaf(tt.y, lrelu(c.y + rr.y, 0.2f), p);
        p = fmaf(tt.z, lrelu(c.z + rr.z, 0.2f), p);
        p = fmaf(tt.w, lrelu(c.w + rr.w, 0.2f), p);
        p += __shfl_xor_sync(FULLMASK, p, 4);
        p += __shfl_xor_sync(FULLMASK, p, 2);
        p += __shfl_xor_sync(FULLMASK, p, 1);        // all 4 heads reduced in-group
        if ((l & 7) == 0)
            out_alpha[(size_t)g_eid[i] * 4 + (l >> 3)] = p;   // raw score
        // branchless single-exp online softmax
        float d = p - m;
        bool pos = d > 0.f;
        float e = __expf(-fabsf(d));
        float sm = pos ? e : 1.f;
        float wn = pos ? 1.f : e;
        s = s * sm + wn;
        a.x = a.x * sm + wn * c.x;
        a.y = a.y * sm + wn * c.y;
        a.z = a.z * sm + wn * c.z;
        a.w = a.w * sm + wn * c.w;
        m = fmaxf(m, p);
        c = n;
    }
    float inv = 1.f / (s + 1e-16f);
    if ((l & 7) == 0) {
        g_m1[4 * w + (l >> 3)]   = m;
        g_inv1[4 * w + (l >> 3)] = inv;
    }
    float4 bb = *(const float4*)&b1[ch];
    float4 h;
    h.x = a.x * inv + bb.x; h.y = a.y * inv + bb.y;
    h.z = a.z * inv + bb.z; h.w = a.w * inv + bb.w;
    *(float4*)&g_h1[(size_t)w * 128 + ch] = h;
    atomicAdd(&sbn[ch],     h.x); atomicAdd(&sbq[ch],     h.x * h.x);
    atomicAdd(&sbn[ch + 1], h.y); atomicAdd(&sbq[ch + 1], h.y * h.y);
    atomicAdd(&sbn[ch + 2], h.z); atomicAdd(&sbq[ch + 2], h.z * h.z);
    atomicAdd(&sbn[ch + 3], h.w); atomicAdd(&sbq[ch + 3], h.w * h.w);
    __syncthreads();
    if (tid < 128) {
        atomicAdd(&g_bnsum[tid], sbn[tid]);
        atomicAdd(&g_bnsq[tid],  sbq[tid]);
    }
}

// ---- alpha_fix: out_alpha[e] = exp(score - m[dst]) * inv[dst], in place ----
__global__ void alpha_fix_k(const void* ei, float* __restrict__ out_alpha) {
    int e = blockIdx.x * blockDim.x + threadIdx.x;
    if (e >= ET) return;
    int d = (e < EE) ? get_edge(ei, 1, e) : (e - EE);
    float4 p  = *(float4*)&out_alpha[(size_t)e * 4];
    float4 mm = *(const float4*)&g_m1[(size_t)d * 4];
    float4 iv = *(const float4*)&g_inv1[(size_t)d * 4];
    p.x = __expf(p.x - mm.x) * iv.x;
    p.y = __expf(p.y - mm.y) * iv.y;
    p.z = __expf(p.z - mm.z) * iv.z;
    p.w = __expf(p.w - mm.w) * iv.w;
    *(float4*)&out_alpha[(size_t)e * 4] = p;
}

__global__ void bnfin_k(const float* __restrict__ gamma, const float* __restrict__ beta) {
    int c = threadIdx.x;
    float mu = g_bnsum[c] * (1.f / NN);
    float var = g_bnsq[c] * (1.f / NN) - mu * mu;
    float sc = gamma[c] * rsqrtf(var + 1e-5f);
    g_bnscale[c] = sc;
    g_bnshift[c] = beta[c] - mu * sc;
}

// ---------------- GEMM 2: (BN+lrelu fused) xl2/xr2 = h1n @ [Wl2|Wr2] --------
__global__ __launch_bounds__(256, 2) void gemm2_k(const float* __restrict__ Wl2,
                                                  const float* __restrict__ Wr2) {
    __shared__ float Ast[32][130];
    __shared__ float Bs[32][68];
    int rowbase = blockIdx.x * 128;
    int tid = threadIdx.x;
    int tx = tid & 15, ty = tid >> 4;
    ull acc[8][2];
#pragma unroll
    for (int i = 0; i < 8; i++) { acc[i][0] = 0ull; acc[i][1] = 0ull; }

    for (int kb = 0; kb < 128; kb += 32) {
#pragma unroll
        for (int p = 0; p < 4; p++) {                 // A: BN + lrelu on load
            int lin = p * 1024 + tid * 4;
            int r = lin >> 5, kkb = lin & 31;
            int grow = rowbase + r;
            float4 v = make_float4(0.f, 0.f, 0.f, 0.f);
            if (grow < NN) {
                v = *(const float4*)&g_h1[(size_t)grow * 128 + kb + kkb];
                int c = kb + kkb;
                v.x = lrelu(v.x * g_bnscale[c]     + g_bnshift[c],     0.01f);
                v.y = lrelu(v.y * g_bnscale[c + 1] + g_bnshift[c + 1], 0.01f);
                v.z = lrelu(v.z * g_bnscale[c + 2] + g_bnshift[c + 2], 0.01f);
                v.w = lrelu(v.w * g_bnscale[c + 3] + g_bnshift[c + 3], 0.01f);
            }
            Ast[kkb + 0][r] = v.x; Ast[kkb + 1][r] = v.y;
            Ast[kkb + 2][r] = v.z; Ast[kkb + 3][r] = v.w;
        }
#pragma unroll
        for (int p = 0; p < 2; p++) {                 // B: 32 k x 64 cols
            int lin = p * 1024 + tid * 4;
            int kk = lin >> 6, c = lin & 63;
            float4 v;
            if (c < 32) v = *(const float4*)&Wl2[(size_t)(kb + kk) * 32 + c];
            else        v = *(const float4*)&Wr2[(size_t)(kb + kk) * 32 + (c - 32)];
            *(float4*)&Bs[kk][c] = v;
        }
        __syncthreads();
#pragma unroll 8
        for (int kk = 0; kk < 32; kk++) {
            ull bv0 = *(ull*)&Bs[kk][2 * tx];
            ull bv1 = *(ull*)&Bs[kk][2 * tx + 32];
#pragma unroll
            for (int rp = 0; rp < 4; rp++) {
                float a0, a1;
                unpack2(*(ull*)&Ast[kk][ty * 8 + 2 * rp], a0, a1);
                ull d0 = pack2(a0, a0), d1 = pack2(a1, a1);
                acc[2 * rp][0]     = fma2(d0, bv0, acc[2 * rp][0]);
                acc[2 * rp][1]     = fma2(d0, bv1, acc[2 * rp][1]);
                acc[2 * rp + 1][0] = fma2(d1, bv0, acc[2 * rp + 1][0]);
                acc[2 * rp + 1][1] = fma2(d1, bv1, acc[2 * rp + 1][1]);
            }
        }
        __syncthreads();
    }
#pragma unroll
    for (int i = 0; i < 8; i++) {
        int grow = rowbase + ty * 8 + i;
        if (grow < NN) {
            *(ull*)&g_xl2[(size_t)grow * 32 + 2 * tx] = acc[i][0];
            *(ull*)&g_xr2[(size_t)grow * 32 + 2 * tx] = acc[i][1];
        }
    }
}

// ---- conv2: 4 dst nodes per warp (8-lane groups, 4 channels/lane) ----------
__global__ void conv2_k(const float* __restrict__ att2, const float* __restrict__ b2,
                        const float* __restrict__ Wout, const float* __restrict__ bout,
                        float* __restrict__ out_logp) {
    int warp = (blockIdx.x * blockDim.x + threadIdx.x) >> 5;  // warp < NN/4
    int l = threadIdx.x & 31;
    int g = l >> 3, lg = l & 7;
    int w = 4 * warp + g;
    int ch = 4 * lg;
    float4 xr = *(const float4*)&g_xr2[(size_t)w * 32 + ch];
    float4 at = *(const float4*)&att2[ch];
    float m = -1e30f, s = 0.f;
    float4 a = make_float4(0.f, 0.f, 0.f, 0.f);
    int beg = g_rowptr[w], end = g_rowptr[w + 1];
    int deg = end - beg;                               // >= 1
    int mx = deg;
    mx = max(mx, __shfl_xor_sync(FULLMASK, mx, 8));
    mx = max(mx, __shfl_xor_sync(FULLMASK, mx, 16));
    float4 c = *(const float4*)&g_xl2[(size_t)g_esrc[beg] * 32 + ch];
    for (int k = 0; k < mx; k++) {
        bool act = k < deg;
        float4 n = c;
        if (k + 1 < deg)
            n = *(const float4*)&g_xl2[(size_t)g_esrc[beg + k + 1] * 32 + ch];
        float p = at.x * lrelu(c.x + xr.x, 0.2f);
        p = fmaf(at.y, lrelu(c.y + xr.y, 0.2f), p);
        p = fmaf(at.z, lrelu(c.z + xr.z, 0.2f), p);
        p = fmaf(at.w, lrelu(c.w + xr.w, 0.2f), p);
        p += __shfl_xor_sync(FULLMASK, p, 4);
        p += __shfl_xor_sync(FULLMASK, p, 2);
        p += __shfl_xor_sync(FULLMASK, p, 1);
        float d = p - m;
        bool pos = (d > 0.f) && act;
        float e = __expf(-fabsf(d));
        float sm = pos ? e : 1.f;
        float wn = act ? (pos ? 1.f : e) : 0.f;
        s = s * sm + wn;
        a.x = a.x * sm + wn * c.x;
        a.y = a.y * sm + wn * c.y;
        a.z = a.z * sm + wn * c.z;
        a.w = a.w * sm + wn * c.w;
        m = pos ? p : m;
        c = n;
    }
    float inv = 1.f / (s + 1e-16f);
    float4 bb = *(const float4*)&b2[ch];
    float hx = lrelu(a.x * inv + bb.x, 0.01f);
    float hy = lrelu(a.y * inv + bb.y, 0.01f);
    float hz = lrelu(a.z * inv + bb.z, 0.01f);
    float hw = lrelu(a.w * inv + bb.w, 0.01f);
    float q0 = hx * Wout[ch * 3] + hy * Wout[(ch + 1) * 3]
             + hz * Wout[(ch + 2) * 3] + hw * Wout[(ch + 3) * 3];
    float q1 = hx * Wout[ch * 3 + 1] + hy * Wout[(ch + 1) * 3 + 1]
             + hz * Wout[(ch + 2) * 3 + 1] + hw * Wout[(ch + 3) * 3 + 1];
    float q2 = hx * Wout[ch * 3 + 2] + hy * Wout[(ch + 1) * 3 + 2]
             + hz * Wout[(ch + 2) * 3 + 2] + hw * Wout[(ch + 3) * 3 + 2];
#pragma unroll
    for (int off = 4; off >= 1; off >>= 1) {
        q0 += __shfl_xor_sync(FULLMASK, q0, off);
        q1 += __shfl_xor_sync(FULLMASK, q1, off);
        q2 += __shfl_xor_sync(FULLMASK, q2, off);
    }
    q0 += bout[0]; q1 += bout[1]; q2 += bout[2];
    float mxq = fmaxf(q0, fmaxf(q1, q2));
    float lse = logf(expf(q0 - mxq) + expf(q1 - mxq) + expf(q2 - mxq)) + mxq;
    if (lg < 3) {
        float z = (lg == 0) ? q0 : (lg == 1) ? q1 : q2;
        out_logp[(size_t)w * 3 + lg] = z - lse;
    }
}

// ---------------- launcher --------------------------------------------------
extern "C" void kernel_launch(void* const* d_in, const int* in_sizes, int n_in,
                              void* d_out, int out_size) {
    const float* x     = (const float*)d_in[0];
    const void*  ei    = d_in[1];
    const float* Wl1   = (const float*)d_in[2];
    const float* Wr1   = (const float*)d_in[3];
    const float* att1  = (const float*)d_in[4];
    const float* b1    = (const float*)d_in[5];
    const float* gamma = (const float*)d_in[6];
    const float* beta  = (const float*)d_in[7];
    const float* Wl2   = (const float*)d_in[8];
    const float* Wr2   = (const float*)d_in[9];
    const float* att2  = (const float*)d_in[10];
    const float* b2    = (const float*)d_in[11];
    const float* Wout  = (const float*)d_in[12];
    const float* bout  = (const float*)d_in[13];
    float* out       = (float*)d_out;
    float* out_logp  = out;
    float* out_alpha = out + (size_t)NN * 3;

    // order chosen so gemm1 sits at captured-launch index 3 for ncu
    init_k<<<(NN + 255) / 256, 256>>>((const int*)ei);
    hist_k<<<(ET + 255) / 256, 256>>>(ei);
    scan1_k<<<NSCAN_BLK, 1024>>>();
    gemm1_k<<<dim3((NN + 127) / 128, 2), 256>>>(x, Wl1, Wr1);
    scan2_k<<<1, 32>>>();
    scan3_k<<<(NN + 255) / 256, 256>>>();
    scatter_k<<<(ET + 255) / 256, 256>>>(ei);
    conv1_k<<<NN / 8, 256>>>(att1, b1, out_alpha);
    alpha_fix_k<<<(ET + 255) / 256, 256>>>(ei, out_alpha);
    bnfin_k<<<1, 128>>>(gamma, beta);
    gemm2_k<<<(NN + 127) / 128, 256>>>(Wl2, Wr2);
    conv2_k<<<NN / 32, 256>>>(att2, b2, Wout, bout, out_logp);
}

// round 10
// speedup vs baseline: 1.7455x; 1.0854x over previous
#include <cuda_runtime.h>
#include <cuda_bf16.h>
#include <cstdint>

#define NN 100000
#define EE 1600000
#define ET 1700000            // EE + NN self loops
#define NT 782                // ceil(NN/128) row tiles
#define NSCAN_BLK 98          // ceil(NN/1024)
#define FULLMASK 0xffffffffu

typedef unsigned long long ull;

// ---------------- scratch (static device globals: no runtime allocation) ----
__device__ float g_xl1[NN * 128];
__device__ float g_xr1[NN * 128];
__device__ float g_h1 [NN * 128];
__device__ float g_xl2[NN * 32];
__device__ float g_xr2[NN * 32];
__device__ float g_m1 [NN * 4];
__device__ float g_inv1[NN * 4];
__device__ __nv_bfloat16 g_Ahi[(size_t)NN * 128];
__device__ __nv_bfloat16 g_Alo[(size_t)NN * 128];
__device__ __nv_bfloat16 g_Bhi[2 * 128 * 128];   // Wt[n][k] per side
__device__ __nv_bfloat16 g_Blo[2 * 128 * 128];
__device__ int   g_deg[NN];
__device__ int   g_cnt[NN];
__device__ int   g_rowptr[NN + 1];
__device__ int   g_esrc[ET];
__device__ int   g_eid [ET];
__device__ int   g_bsum[NSCAN_BLK];
__device__ float g_bnsum[128], g_bnsq[128];
__device__ float g_bnscale[128], g_bnshift[128];
__device__ int   g_is64;

// ---------------- helpers ---------------------------------------------------
__device__ __forceinline__ ull fma2(ull a, ull b, ull c) {
    ull d; asm("fma.rn.f32x2 %0, %1, %2, %3;" : "=l"(d) : "l"(a), "l"(b), "l"(c)); return d;
}
__device__ __forceinline__ ull pack2(float lo, float hi) {
    ull r; asm("mov.b64 %0, {%1, %2};" : "=l"(r) : "f"(lo), "f"(hi)); return r;
}
__device__ __forceinline__ void unpack2(ull v, float& lo, float& hi) {
    asm("mov.b64 {%0, %1}, %2;" : "=f"(lo), "=f"(hi) : "l"(v));
}
__device__ __forceinline__ float lrelu(float v, float s) { return v > 0.f ? v : s * v; }

__device__ __forceinline__ int get_edge(const void* ei, int which, int e) {
    if (g_is64) return (int)((const long long*)ei)[(size_t)which * EE + e];
    return ((const int*)ei)[(size_t)which * EE + e];
}

__device__ __forceinline__ uint32_t smem_u32(const void* p) {
    uint32_t a;
    asm("{ .reg .u64 t; cvta.to.shared.u64 t, %1; cvt.u32.u64 %0, t; }" : "=r"(a) : "l"(p));
    return a;
}

__device__ __forceinline__ void ldsm_x4(uint32_t addr, uint32_t& r0, uint32_t& r1,
                                        uint32_t& r2, uint32_t& r3) {
    asm volatile("ldmatrix.sync.aligned.m8n8.x4.shared.b16 {%0,%1,%2,%3}, [%4];"
                 : "=r"(r0), "=r"(r1), "=r"(r2), "=r"(r3) : "r"(addr));
}
__device__ __forceinline__ void ldsm_x2(uint32_t addr, uint32_t& r0, uint32_t& r1) {
    asm volatile("ldmatrix.sync.aligned.m8n8.x2.shared.b16 {%0,%1}, [%2];"
                 : "=r"(r0), "=r"(r1) : "r"(addr));
}
__device__ __forceinline__ void mma_bf16(float* c, const uint32_t* a, const uint32_t* b) {
    asm volatile(
        "mma.sync.aligned.m16n8k16.row.col.f32.bf16.bf16.f32 "
        "{%0,%1,%2,%3}, {%4,%5,%6,%7}, {%8,%9}, {%0,%1,%2,%3};"
        : "+f"(c[0]), "+f"(c[1]), "+f"(c[2]), "+f"(c[3])
        : "r"(a[0]), "r"(a[1]), "r"(a[2]), "r"(a[3]), "r"(b[0]), "r"(b[1]));
}

// init + edge-index dtype probe (int64 nonneg -> every odd 32-bit word is 0)
__global__ void init_k(const int* ei) {
    int i = blockIdx.x * blockDim.x + threadIdx.x;
    if (i < NN) { g_deg[i] = 0; g_cnt[i] = 0; }
    if (i < 128) { g_bnsum[i] = 0.f; g_bnsq[i] = 0.f; }
    if (i == 0) {
        int z = 1;
        for (int k = 1; k < 129; k += 2) if (ei[k] != 0) { z = 0; break; }
        g_is64 = z;
    }
}

// ---- split x into bf16 hi/lo (row-major) -----------------------------------
__global__ void split_x_k(const float* __restrict__ x) {
    int idx = blockIdx.x * blockDim.x + threadIdx.x;   // over NN*32 float4 chunks
    if (idx >= NN * 32) return;
    float4 v = ((const float4*)x)[idx];
    __nv_bfloat16 h0 = __float2bfloat16(v.x), h1 = __float2bfloat16(v.y);
    __nv_bfloat16 h2 = __float2bfloat16(v.z), h3 = __float2bfloat16(v.w);
    __nv_bfloat162 a01, a23, l01, l23;
    a01.x = h0; a01.y = h1; a23.x = h2; a23.y = h3;
    l01.x = __float2bfloat16(v.x - __bfloat162float(h0));
    l01.y = __float2bfloat16(v.y - __bfloat162float(h1));
    l23.x = __float2bfloat16(v.z - __bfloat162float(h2));
    l23.y = __float2bfloat16(v.w - __bfloat162float(h3));
    *(__nv_bfloat162*)&g_Ahi[(size_t)idx * 4]     = a01;
    *(__nv_bfloat162*)&g_Ahi[(size_t)idx * 4 + 2] = a23;
    *(__nv_bfloat162*)&g_Alo[(size_t)idx * 4]     = l01;
    *(__nv_bfloat162*)&g_Alo[(size_t)idx * 4 + 2] = l23;
}

// ---- transpose W -> Wt[n][k] hi/lo ----------------------------------------
__global__ void build_w2_k(const float* __restrict__ Wl, const float* __restrict__ Wr) {
    int idx = blockIdx.x * blockDim.x + threadIdx.x;   // over 2*128*128
    if (idx >= 2 * 128 * 128) return;
    int side = idx >> 14, n = (idx >> 7) & 127, k = idx & 127;
    const float* W = side ? Wr : Wl;
    float v = W[k * 128 + n];
    __nv_bfloat16 hi = __float2bfloat16(v);
    g_Bhi[idx] = hi;
    g_Blo[idx] = __float2bfloat16(v - __bfloat162float(hi));
}

// ---- GEMM 1 via mma.sync bf16 split: D = AhiBhi + AhiBlo + AloBhi ----------
#define PITCHB 272                       // 136 bf16 per row (ldmatrix conflict-free)
#define SM_ARR 34816                     // 128 * 272
#define SM_TOT (4 * SM_ARR)              // Ahi, Alo, Bhi, Blo

__global__ void __launch_bounds__(512, 1) gemm1_mma_k() {
    extern __shared__ char sm[];
    char* smAhi = sm;
    char* smAlo = sm + SM_ARR;
    char* smBhi = sm + 2 * SM_ARR;
    char* smBlo = sm + 3 * SM_ARR;
    int tid = threadIdx.x;
    int tile = blockIdx.x, side = blockIdx.y;
    float* out = side ? g_xr1 : g_xl1;

    // load smem: A rows (guarded), B rows; 16 int4 per 128-bf16 row
    for (int i = tid; i < 128 * 16; i += 512) {
        int row = i >> 4, c = i & 15;
        int grow = tile * 128 + row;
        int4 vh = make_int4(0, 0, 0, 0), vl = vh;
        if (grow < NN) {
            vh = ((const int4*)g_Ahi)[(size_t)grow * 16 + c];
            vl = ((const int4*)g_Alo)[(size_t)grow * 16 + c];
        }
        *(int4*)(smAhi + row * PITCHB + c * 16) = vh;
        *(int4*)(smAlo + row * PITCHB + c * 16) = vl;
        int4 bh = ((const int4*)g_Bhi)[side * 2048 + i];
        int4 bl = ((const int4*)g_Blo)[side * 2048 + i];
        *(int4*)(smBhi + row * PITCHB + c * 16) = bh;
        *(int4*)(smBlo + row * PITCHB + c * 16) = bl;
    }
    __syncthreads();

    uint32_t sAh = smem_u32(smAhi), sAl = smem_u32(smAlo);
    uint32_t sBh = smem_u32(smBhi), sBl = smem_u32(smBlo);
    int wid = tid >> 5, lane = tid & 31;
    int mrow = (wid >> 2) * 32;          // 0,32,64,96
    int ncol = (wid & 3) * 32;           // 0,32,64,96
    int r8 = lane & 7;
    int amat = lane >> 3;                // 0..3
    int bmat = (lane >> 3) & 1;          // 0..1 (lanes 16-31 mirror, addrs unused)

    float acc[2][4][4];
#pragma unroll
    for (int mt = 0; mt < 2; mt++)
#pragma unroll
        for (int nt = 0; nt < 4; nt++)
#pragma unroll
            for (int q = 0; q < 4; q++) acc[mt][nt][q] = 0.f;

#pragma unroll
    for (int ks = 0; ks < 8; ks++) {
        int k0 = ks * 16;
        uint32_t aHi[2][4], aLo[2][4], bHi[4][2], bLo[4][2];
#pragma unroll
        for (int mt = 0; mt < 2; mt++) {
            int row = mrow + mt * 16 + r8 + (amat & 1) * 8;
            int col = k0 + (amat >> 1) * 8;
            uint32_t off = (uint32_t)(row * PITCHB + col * 2);
            ldsm_x4(sAh + off, aHi[mt][0], aHi[mt][1], aHi[mt][2], aHi[mt][3]);
            ldsm_x4(sAl + off, aLo[mt][0], aLo[mt][1], aLo[mt][2], aLo[mt][3]);
        }
#pragma unroll
        for (int nt = 0; nt < 4; nt++) {
            int row = ncol + nt * 8 + r8;
            int col = k0 + bmat * 8;
            uint32_t off = (uint32_t)(row * PITCHB + col * 2);
            ldsm_x2(sBh + off, bHi[nt][0], bHi[nt][1]);
            ldsm_x2(sBl + off, bLo[nt][0], bLo[nt][1]);
        }
#pragma unroll
        for (int mt = 0; mt < 2; mt++)
#pragma unroll
            for (int nt = 0; nt < 4; nt++) {
                mma_bf16(acc[mt][nt], aHi[mt], bHi[nt]);
                mma_bf16(acc[mt][nt], aHi[mt], bLo[nt]);
                mma_bf16(acc[mt][nt], aLo[mt], bHi[nt]);
            }
    }

    // epilogue: c0,c1 -> row g; c2,c3 -> row g+8; cols ncol+nt*8+2*t4
    int g = lane >> 2, t4 = lane & 3;
#pragma unroll
    for (int mt = 0; mt < 2; mt++) {
        int r0 = tile * 128 + mrow + mt * 16 + g;
#pragma unroll
        for (int nt = 0; nt < 4; nt++) {
            int col = ncol + nt * 8 + 2 * t4;
            if (r0 < NN)
                *(float2*)&out[(size_t)r0 * 128 + col] =
                    make_float2(acc[mt][nt][0], acc[mt][nt][1]);
            if (r0 + 8 < NN)
                *(float2*)&out[(size_t)(r0 + 8) * 128 + col] =
                    make_float2(acc[mt][nt][2], acc[mt][nt][3]);
        }
    }
}

// ---------------- CSR build -------------------------------------------------
__global__ void hist_k(const void* ei) {
    int e = blockIdx.x * blockDim.x + threadIdx.x;
    if (e >= ET) return;
    int d = (e < EE) ? get_edge(ei, 1, e) : (e - EE);
    atomicAdd(&g_deg[d], 1);
}

__global__ void scan1_k() {
    __shared__ int sm[1024];
    int t = threadIdx.x;
    int i = blockIdx.x * 1024 + t;
    int v = (i < NN) ? g_deg[i] : 0;
    sm[t] = v;
    __syncthreads();
    for (int off = 1; off < 1024; off <<= 1) {
        int u = (t >= off) ? sm[t - off] : 0;
        __syncthreads();
        sm[t] += u;
        __syncthreads();
    }
    if (i < NN) g_rowptr[i + 1] = sm[t];
    if (t == 1023) g_bsum[blockIdx.x] = sm[1023];
}

__global__ void scan2_k() {
    if (threadIdx.x == 0 && blockIdx.x == 0) {
        int run = 0;
        for (int i = 0; i < NSCAN_BLK; i++) { run += g_bsum[i]; g_bsum[i] = run; }
    }
}

__global__ void scan3_k() {
    int i = blockIdx.x * blockDim.x + threadIdx.x;
    if (i == 0) g_rowptr[0] = 0;
    if (i < NN) {
        int b = i >> 10;
        if (b > 0) g_rowptr[i + 1] += g_bsum[b - 1];
    }
}

__global__ void scatter_k(const void* ei) {
    int e = blockIdx.x * blockDim.x + threadIdx.x;
    if (e >= ET) return;
    int s, d;
    if (e < EE) { s = get_edge(ei, 0, e); d = get_edge(ei, 1, e); }
    else        { s = e - EE; d = e - EE; }
    int pos = g_rowptr[d] + atomicAdd(&g_cnt[d], 1);
    g_esrc[pos] = s;
    g_eid[pos]  = e;
}

// ---- conv1: warp/dst, lane = 4 channels, head = 8-lane group ---------------
__global__ void conv1_k(const float* __restrict__ att1, const float* __restrict__ b1,
                        float* __restrict__ out_alpha) {
    __shared__ float sbn[128], sbq[128];
    int tid = threadIdx.x;
    if (tid < 128) { sbn[tid] = 0.f; sbq[tid] = 0.f; }
    __syncthreads();
    int w = (blockIdx.x * blockDim.x + tid) >> 5;
    int l = tid & 31;
    int ch = 4 * l;
    float4 rr = *(const float4*)&g_xr1[(size_t)w * 128 + ch];
    float4 tt = *(const float4*)&att1[ch];
    float m = -1e30f, s = 0.f;
    float4 a = make_float4(0.f, 0.f, 0.f, 0.f);
    int beg = g_rowptr[w], end = g_rowptr[w + 1];
    float4 c = *(const float4*)&g_xl1[(size_t)g_esrc[beg] * 128 + ch];
    for (int i = beg; i < end; i++) {
        float4 n = c;
        if (i + 1 < end)
            n = *(const float4*)&g_xl1[(size_t)g_esrc[i + 1] * 128 + ch];
        float p = tt.x * lrelu(c.x + rr.x, 0.2f);
        p = fmaf(tt.y, lrelu(c.y + rr.y, 0.2f), p);
        p = fmaf(tt.z, lrelu(c.z + rr.z, 0.2f), p);
        p = fmaf(tt.w, lrelu(c.w + rr.w, 0.2f), p);
        p += __shfl_xor_sync(FULLMASK, p, 4);
        p += __shfl_xor_sync(FULLMASK, p, 2);
        p += __shfl_xor_sync(FULLMASK, p, 1);
        if ((l & 7) == 0)
            out_alpha[(size_t)g_eid[i] * 4 + (l >> 3)] = p;
        float d = p - m;
        bool pos = d > 0.f;
        float e = __expf(-fabsf(d));
        float sm = pos ? e : 1.f;
        float wn = pos ? 1.f : e;
        s = s * sm + wn;
        a.x = a.x * sm + wn * c.x;
        a.y = a.y * sm + wn * c.y;
        a.z = a.z * sm + wn * c.z;
        a.w = a.w * sm + wn * c.w;
        m = fmaxf(m, p);
        c = n;
    }
    float inv = 1.f / (s + 1e-16f);
    if ((l & 7) == 0) {
        g_m1[4 * w + (l >> 3)]   = m;
        g_inv1[4 * w + (l >> 3)] = inv;
    }
    float4 bb = *(const float4*)&b1[ch];
    float4 h;
    h.x = a.x * inv + bb.x; h.y = a.y * inv + bb.y;
    h.z = a.z * inv + bb.z; h.w = a.w * inv + bb.w;
    *(float4*)&g_h1[(size_t)w * 128 + ch] = h;
    atomicAdd(&sbn[ch],     h.x); atomicAdd(&sbq[ch],     h.x * h.x);
    atomicAdd(&sbn[ch + 1], h.y); atomicAdd(&sbq[ch + 1], h.y * h.y);
    atomicAdd(&sbn[ch + 2], h.z); atomicAdd(&sbq[ch + 2], h.z * h.z);
    atomicAdd(&sbn[ch + 3], h.w); atomicAdd(&sbq[ch + 3], h.w * h.w);
    __syncthreads();
    if (tid < 128) {
        atomicAdd(&g_bnsum[tid], sbn[tid]);
        atomicAdd(&g_bnsq[tid],  sbq[tid]);
    }
}

// ---- alpha_fix: out_alpha[e] = exp(score - m[dst]) * inv[dst], in place ----
__global__ void alpha_fix_k(const void* ei, float* __restrict__ out_alpha) {
    int e = blockIdx.x * blockDim.x + threadIdx.x;
    if (e >= ET) return;
    int d = (e < EE) ? get_edge(ei, 1, e) : (e - EE);
    float4 p  = *(float4*)&out_alpha[(size_t)e * 4];
    float4 mm = *(const float4*)&g_m1[(size_t)d * 4];
    float4 iv = *(const float4*)&g_inv1[(size_t)d * 4];
    p.x = __expf(p.x - mm.x) * iv.x;
    p.y = __expf(p.y - mm.y) * iv.y;
    p.z = __expf(p.z - mm.z) * iv.z;
    p.w = __expf(p.w - mm.w) * iv.w;
    *(float4*)&out_alpha[(size_t)e * 4] = p;
}

__global__ void bnfin_k(const float* __restrict__ gamma, const float* __restrict__ beta) {
    int c = threadIdx.x;
    float mu = g_bnsum[c] * (1.f / NN);
    float var = g_bnsq[c] * (1.f / NN) - mu * mu;
    float sc = gamma[c] * rsqrtf(var + 1e-5f);
    g_bnscale[c] = sc;
    g_bnshift[c] = beta[c] - mu * sc;
}

// ---------------- GEMM 2: (BN+lrelu fused) xl2/xr2 = h1n @ [Wl2|Wr2] --------
__global__ __launch_bounds__(256, 2) void gemm2_k(const float* __restrict__ Wl2,
                                                  const float* __restrict__ Wr2) {
    __shared__ float Ast[32][130];
    __shared__ float Bs[32][68];
    int rowbase = blockIdx.x * 128;
    int tid = threadIdx.x;
    int tx = tid & 15, ty = tid >> 4;
    ull acc[8][2];
#pragma unroll
    for (int i = 0; i < 8; i++) { acc[i][0] = 0ull; acc[i][1] = 0ull; }

    for (int kb = 0; kb < 128; kb += 32) {
#pragma unroll
        for (int p = 0; p < 4; p++) {
            int lin = p * 1024 + tid * 4;
            int r = lin >> 5, kkb = lin & 31;
            int grow = rowbase + r;
            float4 v = make_float4(0.f, 0.f, 0.f, 0.f);
            if (grow < NN) {
                v = *(const float4*)&g_h1[(size_t)grow * 128 + kb + kkb];
                int c = kb + kkb;
                v.x = lrelu(v.x * g_bnscale[c]     + g_bnshift[c],     0.01f);
                v.y = lrelu(v.y * g_bnscale[c + 1] + g_bnshift[c + 1], 0.01f);
                v.z = lrelu(v.z * g_bnscale[c + 2] + g_bnshift[c + 2], 0.01f);
                v.w = lrelu(v.w * g_bnscale[c + 3] + g_bnshift[c + 3], 0.01f);
            }
            Ast[kkb + 0][r] = v.x; Ast[kkb + 1][r] = v.y;
            Ast[kkb + 2][r] = v.z; Ast[kkb + 3][r] = v.w;
        }
#pragma unroll
        for (int p = 0; p < 2; p++) {
            int lin = p * 1024 + tid * 4;
            int kk = lin >> 6, c = lin & 63;
            float4 v;
            if (c < 32) v = *(const float4*)&Wl2[(size_t)(kb + kk) * 32 + c];
            else        v = *(const float4*)&Wr2[(size_t)(kb + kk) * 32 + (c - 32)];
            *(float4*)&Bs[kk][c] = v;
        }
        __syncthreads();
#pragma unroll 8
        for (int kk = 0; kk < 32; kk++) {
            ull bv0 = *(ull*)&Bs[kk][2 * tx];
            ull bv1 = *(ull*)&Bs[kk][2 * tx + 32];
#pragma unroll
            for (int rp = 0; rp < 4; rp++) {
                float a0, a1;
                unpack2(*(ull*)&Ast[kk][ty * 8 + 2 * rp], a0, a1);
                ull d0 = pack2(a0, a0), d1 = pack2(a1, a1);
                acc[2 * rp][0]     = fma2(d0, bv0, acc[2 * rp][0]);
                acc[2 * rp][1]     = fma2(d0, bv1, acc[2 * rp][1]);
                acc[2 * rp + 1][0] = fma2(d1, bv0, acc[2 * rp + 1][0]);
                acc[2 * rp + 1][1] = fma2(d1, bv1, acc[2 * rp + 1][1]);
            }
        }
        __syncthreads();
    }
#pragma unroll
    for (int i = 0; i < 8; i++) {
        int grow = rowbase + ty * 8 + i;
        if (grow < NN) {
            *(ull*)&g_xl2[(size_t)grow * 32 + 2 * tx] = acc[i][0];
            *(ull*)&g_xr2[(size_t)grow * 32 + 2 * tx] = acc[i][1];
        }
    }
}

// ---- conv2: 4 dst nodes per warp (8-lane groups, 4 channels/lane) ----------
__global__ void conv2_k(const float* __restrict__ att2, const float* __restrict__ b2,
                        const float* __restrict__ Wout, const float* __restrict__ bout,
                        float* __restrict__ out_logp) {
    int warp = (blockIdx.x * blockDim.x + threadIdx.x) >> 5;
    int l = threadIdx.x & 31;
    int g = l >> 3, lg = l & 7;
    int w = 4 * warp + g;
    int ch = 4 * lg;
    float4 xr = *(const float4*)&g_xr2[(size_t)w * 32 + ch];
    float4 at = *(const float4*)&att2[ch];
    float m = -1e30f, s = 0.f;
    float4 a = make_float4(0.f, 0.f, 0.f, 0.f);
    int beg = g_rowptr[w], end = g_rowptr[w + 1];
    int deg = end - beg;
    int mx = deg;
    mx = max(mx, __shfl_xor_sync(FULLMASK, mx, 8));
    mx = max(mx, __shfl_xor_sync(FULLMASK, mx, 16));
    float4 c = *(const float4*)&g_xl2[(size_t)g_esrc[beg] * 32 + ch];
    for (int k = 0; k < mx; k++) {
        bool act = k < deg;
        float4 n = c;
        if (k + 1 < deg)
            n = *(const float4*)&g_xl2[(size_t)g_esrc[beg + k + 1] * 32 + ch];
        float p = at.x * lrelu(c.x + xr.x, 0.2f);
        p = fmaf(at.y, lrelu(c.y + xr.y, 0.2f), p);
        p = fmaf(at.z, lrelu(c.z + xr.z, 0.2f), p);
        p = fmaf(at.w, lrelu(c.w + xr.w, 0.2f), p);
        p += __shfl_xor_sync(FULLMASK, p, 4);
        p += __shfl_xor_sync(FULLMASK, p, 2);
        p += __shfl_xor_sync(FULLMASK, p, 1);
        float d = p - m;
        bool pos = (d > 0.f) && act;
        float e = __expf(-fabsf(d));
        float sm = pos ? e : 1.f;
        float wn = act ? (pos ? 1.f : e) : 0.f;
        s = s * sm + wn;
        a.x = a.x * sm + wn * c.x;
        a.y = a.y * sm + wn * c.y;
        a.z = a.z * sm + wn * c.z;
        a.w = a.w * sm + wn * c.w;
        m = pos ? p : m;
        c = n;
    }
    float inv = 1.f / (s + 1e-16f);
    float4 bb = *(const float4*)&b2[ch];
    float hx = lrelu(a.x * inv + bb.x, 0.01f);
    float hy = lrelu(a.y * inv + bb.y, 0.01f);
    float hz = lrelu(a.z * inv + bb.z, 0.01f);
    float hw = lrelu(a.w * inv + bb.w, 0.01f);
    float q0 = hx * Wout[ch * 3] + hy * Wout[(ch + 1) * 3]
             + hz * Wout[(ch + 2) * 3] + hw * Wout[(ch + 3) * 3];
    float q1 = hx * Wout[ch * 3 + 1] + hy * Wout[(ch + 1) * 3 + 1]
             + hz * Wout[(ch + 2) * 3 + 1] + hw * Wout[(ch + 3) * 3 + 1];
    float q2 = hx * Wout[ch * 3 + 2] + hy * Wout[(ch + 1) * 3 + 2]
             + hz * Wout[(ch + 2) * 3 + 2] + hw * Wout[(ch + 3) * 3 + 2];
#pragma unroll
    for (int off = 4; off >= 1; off >>= 1) {
        q0 += __shfl_xor_sync(FULLMASK, q0, off);
        q1 += __shfl_xor_sync(FULLMASK, q1, off);
        q2 += __shfl_xor_sync(FULLMASK, q2, off);
    }
    q0 += bout[0]; q1 += bout[1]; q2 += bout[2];
    float mxq = fmaxf(q0, fmaxf(q1, q2));
    float lse = logf(expf(q0 - mxq) + expf(q1 - mxq) + expf(q2 - mxq)) + mxq;
    if (lg < 3) {
        float z = (lg == 0) ? q0 : (lg == 1) ? q1 : q2;
        out_logp[(size_t)w * 3 + lg] = z - lse;
    }
}

// ---------------- launcher --------------------------------------------------
extern "C" void kernel_launch(void* const* d_in, const int* in_sizes, int n_in,
                              void* d_out, int out_size) {
    const float* x     = (const float*)d_in[0];
    const void*  ei    = d_in[1];
    const float* Wl1   = (const float*)d_in[2];
    const float* Wr1   = (const float*)d_in[3];
    const float* att1  = (const float*)d_in[4];
    const float* b1    = (const float*)d_in[5];
    const float* gamma = (const float*)d_in[6];
    const float* beta  = (const float*)d_in[7];
    const float* Wl2   = (const float*)d_in[8];
    const float* Wr2   = (const float*)d_in[9];
    const float* att2  = (const float*)d_in[10];
    const float* b2    = (const float*)d_in[11];
    const float* Wout  = (const float*)d_in[12];
    const float* bout  = (const float*)d_in[13];
    float* out       = (float*)d_out;
    float* out_logp  = out;
    float* out_alpha = out + (size_t)NN * 3;

    cudaFuncSetAttribute(gemm1_mma_k, cudaFuncAttributeMaxDynamicSharedMemorySize, SM_TOT);

    // order chosen so gemm1_mma sits at captured-launch index 3 for ncu
    init_k<<<(NN + 255) / 256, 256>>>((const int*)ei);
    split_x_k<<<(NN * 32 + 255) / 256, 256>>>(x);
    build_w2_k<<<(2 * 128 * 128 + 255) / 256, 256>>>(Wl1, Wr1);
    gemm1_mma_k<<<dim3(NT, 2), 512, SM_TOT>>>();
    hist_k<<<(ET + 255) / 256, 256>>>(ei);
    scan1_k<<<NSCAN_BLK, 1024>>>();
    scan2_k<<<1, 32>>>();
    scan3_k<<<(NN + 255) / 256, 256>>>();
    scatter_k<<<(ET + 255) / 256, 256>>>(ei);
    conv1_k<<<NN / 8, 256>>>(att1, b1, out_alpha);
    alpha_fix_k<<<(ET + 255) / 256, 256>>>(ei, out_alpha);
    bnfin_k<<<1, 128>>>(gamma, beta);
    gemm2_k<<<(NN + 127) / 128, 256>>>(Wl2, Wr2);
    conv2_k<<<NN / 32, 256>>>(att2, b2, Wout, bout, out_logp);
}